// round 11
// baseline (speedup 1.0000x reference)
#include <cuda_runtime.h>
#include <cuda_fp16.h>
#include <math.h>
#include <stdint.h>

// Problem constants
#define BB   2
#define SS   2048
#define EE   2048
#define HH   16
#define DD   128
#define MTOT (BB*SS)      // 4096
#define NQKV (3*EE)       // 6144
#define KDIM EE           // 2048

// ---------------------------------------------------------------------------
// Scratch (device globals; no allocation allowed)
// ---------------------------------------------------------------------------
__device__ float g_q[(size_t)BB*HH*SS*DD];     // fp32 (pre-RoPE)
__device__ float g_k[(size_t)BB*HH*SS*DD];
__device__ float g_cos[SS*64];
__device__ float g_sin[SS*64];

__device__ __half g_qh[(size_t)BB*HH*SS*DD];   // RoPE'd Q hi
__device__ __half g_ql[(size_t)BB*HH*SS*DD];   // RoPE'd Q lo
__device__ __half g_kh[(size_t)BB*HH*SS*DD];   // RoPE'd K (single-rounded)
__device__ __half g_vh[(size_t)BB*HH*SS*DD];   // V (single-rounded)

__device__ __half g_xh[(size_t)MTOT*KDIM];     // x hi
__device__ __half g_xl[(size_t)MTOT*KDIM];     // x lo
__device__ __half g_wqh[(size_t)NQKV*KDIM];    // Wqkv (single-rounded)
__device__ __half g_owh[(size_t)EE*KDIM];      // out_w (single-rounded)
__device__ __half g_ch[(size_t)MTOT*EE];       // ctx hi
__device__ __half g_cl[(size_t)MTOT*EE];       // ctx lo

// ---------------------------------------------------------------------------
// Baseline-PTX helpers (sm_80+)
// ---------------------------------------------------------------------------
__device__ __forceinline__ uint32_t smem_u32(const void* p) {
    uint32_t a;
    asm("{ .reg .u64 t; cvta.to.shared.u64 t, %1; cvt.u32.u64 %0, t; }"
        : "=r"(a) : "l"(p));
    return a;
}

#define CP_ASYNC16(dst, src) \
    asm volatile("cp.async.cg.shared.global [%0], [%1], 16;" \
                 :: "r"(dst), "l"(src) : "memory")
#define CP_COMMIT() asm volatile("cp.async.commit_group;" ::: "memory")

__device__ __forceinline__ void ldmatrix_x4(uint32_t* r, uint32_t addr) {
    asm volatile("ldmatrix.sync.aligned.m8n8.x4.shared.b16 {%0,%1,%2,%3}, [%4];"
                 : "=r"(r[0]), "=r"(r[1]), "=r"(r[2]), "=r"(r[3]) : "r"(addr));
}
__device__ __forceinline__ void ldmatrix_x4_t(uint32_t* r, uint32_t addr) {
    asm volatile("ldmatrix.sync.aligned.m8n8.x4.trans.shared.b16 {%0,%1,%2,%3}, [%4];"
                 : "=r"(r[0]), "=r"(r[1]), "=r"(r[2]), "=r"(r[3]) : "r"(addr));
}

// fp16 inputs, fp32 accumulate
__device__ __forceinline__ void mma16816(float* c,
    uint32_t a0, uint32_t a1, uint32_t a2, uint32_t a3, uint32_t b0, uint32_t b1)
{
    asm volatile(
        "mma.sync.aligned.m16n8k16.row.col.f32.f16.f16.f32 "
        "{%0,%1,%2,%3}, {%4,%5,%6,%7}, {%8,%9}, {%0,%1,%2,%3};"
        : "+f"(c[0]), "+f"(c[1]), "+f"(c[2]), "+f"(c[3])
        : "r"(a0), "r"(a1), "r"(a2), "r"(a3), "r"(b0), "r"(b1));
}

__device__ __forceinline__ void split1(float x, __half& h, __half& l) {
    h = __float2half_rn(x);
    l = __float2half_rn(x - __half2float(h));
}
__device__ __forceinline__ void pack_split(float x, float y,
                                           uint32_t& hi, uint32_t& lo) {
    __half hx, lx, hy, ly;
    split1(x, hx, lx); split1(y, hy, ly);
    __half2 hp = __halves2half2(hx, hy);
    __half2 lp = __halves2half2(lx, ly);
    hi = *(uint32_t*)&hp;
    lo = *(uint32_t*)&lp;
}

// ---------------------------------------------------------------------------
// fp32 -> (hi, lo) fp16 split (bulk) and hi-only convert
// ---------------------------------------------------------------------------
__global__ void split_kernel(const float* __restrict__ src,
                             __half* __restrict__ hi,
                             __half* __restrict__ lo, int n)
{
    int i4 = (blockIdx.x * blockDim.x + threadIdx.x) << 2;
    if (i4 >= n) return;
    float4 v = *(const float4*)(src + i4);
    float xs[4] = {v.x, v.y, v.z, v.w};
    __half h[4], l[4];
#pragma unroll
    for (int q = 0; q < 4; q++) split1(xs[q], h[q], l[q]);
    *(uint2*)(hi + i4) = *(uint2*)h;
    *(uint2*)(lo + i4) = *(uint2*)l;
}

__global__ void cvt_hi_kernel(const float* __restrict__ src,
                              __half* __restrict__ hi, int n)
{
    int i4 = (blockIdx.x * blockDim.x + threadIdx.x) << 2;
    if (i4 >= n) return;
    float4 v = *(const float4*)(src + i4);
    __half h[4];
    h[0] = __float2half_rn(v.x); h[1] = __float2half_rn(v.y);
    h[2] = __float2half_rn(v.z); h[3] = __float2half_rn(v.w);
    *(uint2*)(hi + i4) = *(uint2*)h;
}

// ---------------------------------------------------------------------------
// RoPE table
// ---------------------------------------------------------------------------
__global__ void rope_table_kernel()
{
    int idx = blockIdx.x * blockDim.x + threadIdx.x;
    if (idx >= SS * 64) return;
    int j = idx & 63;
    int s = idx >> 6;
    double denom = pow(10000.0, ((double)(2 * j)) / 128.0);
    float invf = (float)(1.0 / denom);
    float ph = (float)s * invf;
    double p = (double)ph;
    g_cos[idx] = (float)cos(p);
    g_sin[idx] = (float)sin(p);
}

// RoPE on fp32 q/k. Q -> (hi, lo) fp16 split; K -> single-rounded fp16.
__global__ void rope_split_kernel()
{
    int idx = blockIdx.x * blockDim.x + threadIdx.x;   // 2*65536*64
    int j      = idx & 63;
    int r      = idx >> 6;
    int bhs    = r & (BB*HH*SS - 1);
    int tensor = r >> 16;
    int s      = bhs & (SS - 1);

    size_t base = (size_t)bhs * DD;
    float c  = g_cos[(s << 6) + j];
    float sn = g_sin[(s << 6) + j];
    if (tensor == 0) {
        float x1 = g_q[base + j];
        float x2 = g_q[base + j + 64];
        float y1 = x1 * c - x2 * sn;
        float y2 = x2 * c + x1 * sn;
        __half h, l;
        split1(y1, h, l); g_qh[base + j] = h;      g_ql[base + j] = l;
        split1(y2, h, l); g_qh[base + j + 64] = h; g_ql[base + j + 64] = l;
    } else {
        float x1 = g_k[base + j];
        float x2 = g_k[base + j + 64];
        float y1 = x1 * c - x2 * sn;
        float y2 = x2 * c + x1 * sn;
        g_kh[base + j]      = __float2half_rn(y1);
        g_kh[base + j + 64] = __float2half_rn(y2);
    }
}

// ---------------------------------------------------------------------------
// mma.sync fp16x2 GEMM: C = Ah*Bh + Al*Bh + bias  (A split, B single-rounded)
// Tile: CTA 128x128, warp 64x32, K-chunk 32.
// 4-stage cp.async pipeline, ONE __syncthreads per chunk (stage t+3 never
// aliases stage t). Fragments hoisted per k16 half-chunk (10 ldmatrix ->
// 16 MMAs) to keep register pressure moderate.
// MODE 0: q,k fp32 + v fp16. MODE 1: C fp32.
// ---------------------------------------------------------------------------
#define GK_CHUNK   32
#define TILE_BYTES 10240            // 128 rows * 80B (32 fp16 + 8 pad)
#define STAGE_BYTES (3*TILE_BYTES)  // Ah, Al, Bh
#define GSTAGES    4
#define GEMM_SMEM  (GSTAGES*STAGE_BYTES)   // 122880 B

__device__ __forceinline__ void gemm_load_stage(
    uint32_t stg, const __half* const* tp, int K, int kt, int tid)
{
#pragma unroll
    for (int t = 0; t < 3; t++) {
        const __half* p = tp[t];
#pragma unroll
        for (int i = 0; i < 2; i++) {
            int slot = tid + (i << 8);
            int row  = slot >> 2;
            int c    = slot & 3;
            uint32_t dst = stg + t * TILE_BYTES + row * 80 + c * 16;
            const void* src = p + (size_t)row * K + kt + c * 8;
            CP_ASYNC16(dst, src);
        }
    }
    CP_COMMIT();
}

template<int MODE>
__global__ __launch_bounds__(256) void gemm_mma(
    const __half* __restrict__ Ah, const __half* __restrict__ Al,
    const __half* __restrict__ Bh,
    const float* __restrict__ bias, float* __restrict__ C,
    int M, int N, int K)
{
    extern __shared__ char smch[];
    const uint32_t sbase = smem_u32(smch);
    const int tid  = threadIdx.x;
    const int wid  = tid >> 5;
    const int lane = tid & 31;
    const int wm   = wid & 1;
    const int wn   = wid >> 1;
    const int m0   = blockIdx.y << 7;
    const int n0   = blockIdx.x << 7;

    const __half* tp[3] = {
        Ah + (size_t)m0 * K, Al + (size_t)m0 * K, Bh + (size_t)n0 * K };

    float c[4][4][4];
#pragma unroll
    for (int i = 0; i < 4; i++)
#pragma unroll
        for (int j = 0; j < 4; j++)
#pragma unroll
            for (int q = 0; q < 4; q++) c[i][j][q] = 0.f;

    const int T = K / GK_CHUNK;        // 64

    gemm_load_stage(sbase + 0 * STAGE_BYTES, tp, K, 0 * GK_CHUNK, tid);
    gemm_load_stage(sbase + 1 * STAGE_BYTES, tp, K, 1 * GK_CHUNK, tid);
    gemm_load_stage(sbase + 2 * STAGE_BYTES, tp, K, 2 * GK_CHUNK, tid);

    const int rsel = lane & 15;
    const int csel = (lane >> 4) << 3;

#pragma unroll 1
    for (int t = 0; t < T; t++) {
        int rem = (T - 1) - t;
        if (rem >= 2)      asm volatile("cp.async.wait_group 2;" ::: "memory");
        else if (rem == 1) asm volatile("cp.async.wait_group 1;" ::: "memory");
        else               asm volatile("cp.async.wait_group 0;" ::: "memory");
        __syncthreads();

        // issue loads for stage t+3 into buffer (t+3)&3 = (t-1)&3; all reads
        // of its previous occupant finished before this iteration's sync
        if (t + 3 < T)
            gemm_load_stage(sbase + ((t+3) & 3) * STAGE_BYTES,
                            tp, K, (t+3) * GK_CHUNK, tid);

        const uint32_t stg = sbase + (t & 3) * STAGE_BYTES;
        const uint32_t aAh = stg;
        const uint32_t aAl = stg + TILE_BYTES;
        const uint32_t aB  = stg + 2*TILE_BYTES;

#pragma unroll
        for (int k16 = 0; k16 < 2; k16++) {
            const int koff = (csel + k16*16)*2;
            // hoist this half-chunk's 10 ldmatrix ahead of its 16 MMAs
            uint32_t a0[4][4], a1[4][4], bf[2][4];
#pragma unroll
            for (int i = 0; i < 4; i++) {
                ldmatrix_x4(a0[i], aAh + (wm*64 + i*16 + rsel)*80 + koff);
                ldmatrix_x4(a1[i], aAl + (wm*64 + i*16 + rsel)*80 + koff);
            }
#pragma unroll
            for (int j16 = 0; j16 < 2; j16++)
                ldmatrix_x4(bf[j16], aB + (wn*32 + j16*16 + rsel)*80 + koff);

#pragma unroll
            for (int i = 0; i < 4; i++)
#pragma unroll
                for (int j16 = 0; j16 < 2; j16++) {
                    mma16816(c[i][j16*2+0],
                             a0[i][0], a0[i][1], a0[i][2], a0[i][3],
                             bf[j16][0], bf[j16][2]);
                    mma16816(c[i][j16*2+1],
                             a0[i][0], a0[i][1], a0[i][2], a0[i][3],
                             bf[j16][1], bf[j16][3]);
                }
#pragma unroll
            for (int i = 0; i < 4; i++)
#pragma unroll
                for (int j16 = 0; j16 < 2; j16++) {
                    mma16816(c[i][j16*2+0],
                             a1[i][0], a1[i][1], a1[i][2], a1[i][3],
                             bf[j16][0], bf[j16][2]);
                    mma16816(c[i][j16*2+1],
                             a1[i][0], a1[i][1], a1[i][2], a1[i][3],
                             bf[j16][1], bf[j16][3]);
                }
        }
        // no second __syncthreads: next overwrite targets (t+4)&3, protected
        // by the sync at iteration t+1
    }

#pragma unroll
    for (int i = 0; i < 4; i++) {
        int rowA = m0 + wm*64 + i*16 + (lane >> 2);
#pragma unroll
        for (int j = 0; j < 4; j++) {
            int col = n0 + wn*32 + j*8 + (lane & 3)*2;
            float b0 = bias[col], b1 = bias[col+1];
            float2 lo2 = make_float2(c[i][j][0] + b0, c[i][j][1] + b1);
            float2 hi2 = make_float2(c[i][j][2] + b0, c[i][j][3] + b1);
#pragma unroll
            for (int half = 0; half < 2; half++) {
                int row = rowA + half*8;
                float2 v = half ? hi2 : lo2;
                if (MODE == 0) {
                    int which = col >> 11;
                    int h = (col >> 7) & (HH - 1);
                    int d = col & (DD - 1);
                    int bb = row >> 11;
                    int s = row & (SS - 1);
                    size_t off = (((size_t)bb * HH + h) * SS + s) * DD + d;
                    if (which == 2) {
                        __half2 hp = __halves2half2(__float2half_rn(v.x),
                                                    __float2half_rn(v.y));
                        *(__half2*)&g_vh[off] = hp;
                    } else {
                        float* dst = which ? g_k : g_q;
                        *(float2*)&dst[off] = v;
                    }
                } else {
                    *(float2*)&C[(size_t)row * N + col] = v;
                }
            }
        }
    }
}

// ---------------------------------------------------------------------------
// Tensor-core flash attention, fp16x2 (unchanged from R8 pass):
//   S = Qh*Kh + Ql*Kh  (Q split, K single-rounded)
//   O += Ph*Vh + Pl*Vh (P split, V single-rounded)
// ---------------------------------------------------------------------------
#define AT_ROWB  272                    // 128 fp16 + 8 pad
#define Q_BYTES  (128*AT_ROWB)          // 34816
#define KV_TILE  (64*AT_ROWB)           // 17408
#define ATT_SMEM (2*Q_BYTES + 2*KV_TILE)  // 104448

__global__ __launch_bounds__(256, 1) void attn_mma_kernel()
{
    extern __shared__ char smc[];
    const uint32_t sb  = smem_u32(smc);
    const uint32_t sQh = sb;
    const uint32_t sQl = sb + Q_BYTES;
    const uint32_t sKh = sb + 2*Q_BYTES;
    const uint32_t sVh = sKh + KV_TILE;

    const int tid  = threadIdx.x;
    const int wid  = tid >> 5;
    const int lane = tid & 31;
    const int q0 = blockIdx.x << 7;
    const int h  = blockIdx.y;
    const int b  = blockIdx.z;

    const size_t head_off = ((size_t)b * HH + h) * SS * DD;
    const __half* Qhg = g_qh + head_off + (size_t)q0 * DD;
    const __half* Qlg = g_ql + head_off + (size_t)q0 * DD;
    const __half* Khg = g_kh + head_off;
    const __half* Vhg = g_vh + head_off;

    auto load_k = [&](int kt) {
#pragma unroll
        for (int i = 0; i < 4; i++) {
            int idx = tid + (i << 8);          // 0..1023
            int row = idx >> 4, c = idx & 15;
            CP_ASYNC16(sKh + row*AT_ROWB + c*16, Khg + (size_t)(kt+row)*DD + c*8);
        }
        CP_COMMIT();
    };
    auto load_v = [&](int kt) {
#pragma unroll
        for (int i = 0; i < 4; i++) {
            int idx = tid + (i << 8);
            int row = idx >> 4, c = idx & 15;
            CP_ASYNC16(sVh + row*AT_ROWB + c*16, Vhg + (size_t)(kt+row)*DD + c*8);
        }
        CP_COMMIT();
    };

    // ---- prologue: Q (hi+lo) + K0 + V0, one commit group ----
    {
#pragma unroll
        for (int i = 0; i < 8; i++) {
            int cidx = tid + (i << 8);         // 0..2047
            int row = cidx >> 4, c = cidx & 15;
            CP_ASYNC16(sQh + row*AT_ROWB + c*16, Qhg + (size_t)row*DD + c*8);
            CP_ASYNC16(sQl + row*AT_ROWB + c*16, Qlg + (size_t)row*DD + c*8);
        }
#pragma unroll
        for (int i = 0; i < 8; i++) {
            int idx = tid + (i << 8);          // 0..2047: Kh, Vh tiles
            int arr = idx >> 10;               // 0..1
            int row = (idx >> 4) & 63;
            int c   = idx & 15;
            const __half* src = arr ? Vhg : Khg;
            uint32_t dstb = arr ? sVh : sKh;
            CP_ASYNC16(dstb + row*AT_ROWB + c*16, src + (size_t)row*DD + c*8);
        }
        CP_COMMIT();
    }

    float o[16][4];
#pragma unroll
    for (int n = 0; n < 16; n++)
#pragma unroll
        for (int q = 0; q < 4; q++) o[n][q] = 0.f;
    float m0 = -1e30f, m1 = -1e30f, l0 = 0.f, l1 = 0.f;

    const float scale = 0.088388347648318447f;   // 1/sqrt(128)
    const int wq = wid << 4;
    const int rsel = lane & 15;
    const int csel = (lane >> 4) << 3;
    const int NT = SS / 64;                      // 32

#pragma unroll 1
    for (int t = 0; t < NT; t++) {
        // ---- K(t) ready? ----
        if (t == 0) asm volatile("cp.async.wait_group 0;" ::: "memory");
        else        asm volatile("cp.async.wait_group 1;" ::: "memory");
        __syncthreads();

        // ---- scores S = Qh*Kh + Ql*Kh ----
        float S[8][4];
#pragma unroll
        for (int j = 0; j < 8; j++)
#pragma unroll
            for (int q = 0; q < 4; q++) S[j][q] = 0.f;

#pragma unroll
        for (int ds = 0; ds < 8; ds++) {
            const int doff = (ds*16 + csel) * 2;
            uint32_t qh[4], ql[4], kh[4][4];
            ldmatrix_x4(qh, sQh + (wq + rsel)*AT_ROWB + doff);
            ldmatrix_x4(ql, sQl + (wq + rsel)*AT_ROWB + doff);
#pragma unroll
            for (int j16 = 0; j16 < 4; j16++)
                ldmatrix_x4(kh[j16], sKh + (j16*16 + rsel)*AT_ROWB + doff);
#pragma unroll
            for (int j16 = 0; j16 < 4; j16++) {
                mma16816(S[2*j16],   qh[0], qh[1], qh[2], qh[3], kh[j16][0], kh[j16][2]);
                mma16816(S[2*j16+1], qh[0], qh[1], qh[2], qh[3], kh[j16][1], kh[j16][3]);
            }
#pragma unroll
            for (int j16 = 0; j16 < 4; j16++) {
                mma16816(S[2*j16],   ql[0], ql[1], ql[2], ql[3], kh[j16][0], kh[j16][2]);
                mma16816(S[2*j16+1], ql[0], ql[1], ql[2], ql[3], kh[j16][1], kh[j16][3]);
            }
        }
        __syncthreads();                 // all warps done reading K tile

        if (t + 1 < NT) load_k((t + 1) << 6);

        // ---- online softmax ----
        float mx0 = -1e30f, mx1 = -1e30f;
#pragma unroll
        for (int j = 0; j < 8; j++) {
            S[j][0] *= scale; S[j][1] *= scale;
            S[j][2] *= scale; S[j][3] *= scale;
            mx0 = fmaxf(mx0, fmaxf(S[j][0], S[j][1]));
            mx1 = fmaxf(mx1, fmaxf(S[j][2], S[j][3]));
        }
        mx0 = fmaxf(mx0, __shfl_xor_sync(0xffffffffu, mx0, 1));
        mx0 = fmaxf(mx0, __shfl_xor_sync(0xffffffffu, mx0, 2));
        mx1 = fmaxf(mx1, __shfl_xor_sync(0xffffffffu, mx1, 1));
        mx1 = fmaxf(mx1, __shfl_xor_sync(0xffffffffu, mx1, 2));

        float mn0 = fmaxf(m0, mx0), mn1 = fmaxf(m1, mx1);
        float fac0 = __expf(m0 - mn0), fac1 = __expf(m1 - mn1);
        float rs0 = 0.f, rs1 = 0.f;
#pragma unroll
        for (int j = 0; j < 8; j++) {
            S[j][0] = __expf(S[j][0] - mn0); rs0 += S[j][0];
            S[j][1] = __expf(S[j][1] - mn0); rs0 += S[j][1];
            S[j][2] = __expf(S[j][2] - mn1); rs1 += S[j][2];
            S[j][3] = __expf(S[j][3] - mn1); rs1 += S[j][3];
        }
        rs0 += __shfl_xor_sync(0xffffffffu, rs0, 1);
        rs0 += __shfl_xor_sync(0xffffffffu, rs0, 2);
        rs1 += __shfl_xor_sync(0xffffffffu, rs1, 1);
        rs1 += __shfl_xor_sync(0xffffffffu, rs1, 2);
        l0 = l0 * fac0 + rs0; m0 = mn0;
        l1 = l1 * fac1 + rs1; m1 = mn1;
#pragma unroll
        for (int n = 0; n < 16; n++) {
            o[n][0] *= fac0; o[n][1] *= fac0;
            o[n][2] *= fac1; o[n][3] *= fac1;
        }

        // ---- V(t) ready? ----
        if (t + 1 < NT) asm volatile("cp.async.wait_group 1;" ::: "memory");
        else            asm volatile("cp.async.wait_group 0;" ::: "memory");
        __syncthreads();

        // ---- O += Ph*Vh + Pl*Vh ----
#pragma unroll
        for (int kk = 0; kk < 4; kk++) {
            uint32_t ah[4], al[4];
            pack_split(S[2*kk][0],   S[2*kk][1],   ah[0], al[0]);
            pack_split(S[2*kk][2],   S[2*kk][3],   ah[1], al[1]);
            pack_split(S[2*kk+1][0], S[2*kk+1][1], ah[2], al[2]);
            pack_split(S[2*kk+1][2], S[2*kk+1][3], ah[3], al[3]);
            const uint32_t vrow = (kk*16 + rsel)*AT_ROWB;
#pragma unroll
            for (int db = 0; db < 8; db += 2) {
                uint32_t vh[2][4];
                ldmatrix_x4_t(vh[0], sVh + vrow + (db*16 + csel)*2);
                ldmatrix_x4_t(vh[1], sVh + vrow + ((db+1)*16 + csel)*2);
#pragma unroll
                for (int u = 0; u < 2; u++) {
                    int n = (db+u)*2;
                    mma16816(o[n],   ah[0], ah[1], ah[2], ah[3], vh[u][0], vh[u][1]);
                    mma16816(o[n+1], ah[0], ah[1], ah[2], ah[3], vh[u][2], vh[u][3]);
                }
#pragma unroll
                for (int u = 0; u < 2; u++) {
                    int n = (db+u)*2;
                    mma16816(o[n],   al[0], al[1], al[2], al[3], vh[u][0], vh[u][1]);
                    mma16816(o[n+1], al[0], al[1], al[2], al[3], vh[u][2], vh[u][3]);
                }
            }
        }
        __syncthreads();                 // all warps done reading V tile

        if (t + 1 < NT) load_v((t + 1) << 6);
    }

    // ---- epilogue: normalize, split to hi/lo fp16, write ctx ----
    const int g  = lane >> 2;
    const int tg = lane & 3;
    const float inv0 = 1.f / l0;
    const float inv1 = 1.f / l1;
    const int s0 = q0 + wq + g;
    const int s1 = s0 + 8;
#pragma unroll
    for (int n = 0; n < 16; n++) {
        int col = h*DD + 8*n + 2*tg;
        {
            size_t off = (size_t)(b*SS + s0) * EE + col;
            __half h0, l0b, h1, l1b;
            split1(o[n][0] * inv0, h0, l0b);
            split1(o[n][1] * inv0, h1, l1b);
            *(__half2*)&g_ch[off] = __halves2half2(h0, h1);
            *(__half2*)&g_cl[off] = __halves2half2(l0b, l1b);
        }
        {
            size_t off = (size_t)(b*SS + s1) * EE + col;
            __half h0, l0b, h1, l1b;
            split1(o[n][2] * inv1, h0, l0b);
            split1(o[n][3] * inv1, h1, l1b);
            *(__half2*)&g_ch[off] = __halves2half2(h0, h1);
            *(__half2*)&g_cl[off] = __halves2half2(l0b, l1b);
        }
    }
}

// ---------------------------------------------------------------------------
// Launch
// ---------------------------------------------------------------------------
extern "C" void kernel_launch(void* const* d_in, const int* in_sizes, int n_in,
                              void* d_out, int out_size)
{
    (void)in_sizes; (void)n_in; (void)out_size;
    const float* x      = (const float*)d_in[0];
    const float* Wqkv_w = (const float*)d_in[1];
    const float* Wqkv_b = (const float*)d_in[2];
    const float* out_w  = (const float*)d_in[3];
    const float* out_b  = (const float*)d_in[4];
    float* out = (float*)d_out;

    __half *xh, *xl, *wqh, *owh, *ch, *cl;
    cudaGetSymbolAddress((void**)&xh,  g_xh);
    cudaGetSymbolAddress((void**)&xl,  g_xl);
    cudaGetSymbolAddress((void**)&wqh, g_wqh);
    cudaGetSymbolAddress((void**)&owh, g_owh);
    cudaGetSymbolAddress((void**)&ch,  g_ch);
    cudaGetSymbolAddress((void**)&cl,  g_cl);

    cudaFuncSetAttribute(attn_mma_kernel, cudaFuncAttributeMaxDynamicSharedMemorySize,
                         ATT_SMEM);
    cudaFuncSetAttribute(gemm_mma<0>, cudaFuncAttributeMaxDynamicSharedMemorySize,
                         GEMM_SMEM);
    cudaFuncSetAttribute(gemm_mma<1>, cudaFuncAttributeMaxDynamicSharedMemorySize,
                         GEMM_SMEM);

    rope_table_kernel<<<(SS * 64 + 255) / 256, 256>>>();

    split_kernel<<<(MTOT*KDIM/4 + 255) / 256, 256>>>(x, xh, xl, MTOT*KDIM);
    cvt_hi_kernel<<<(NQKV*KDIM/4 + 255) / 256, 256>>>(Wqkv_w, wqh, NQKV*KDIM);
    cvt_hi_kernel<<<(EE*KDIM/4 + 255) / 256, 256>>>(out_w, owh, EE*KDIM);

    gemm_mma<0><<<dim3(NQKV/128, MTOT/128), 256, GEMM_SMEM>>>(
        xh, xl, wqh, Wqkv_b, nullptr, MTOT, NQKV, KDIM);

    rope_split_kernel<<<(2 * BB * HH * SS * 64) / 256, 256>>>();

    attn_mma_kernel<<<dim3(SS/128, HH, BB), 256, ATT_SMEM>>>();

    gemm_mma<1><<<dim3(EE/128, MTOT/128), 256, GEMM_SMEM>>>(
        ch, cl, owh, out_b, out, MTOT, EE, KDIM);
}

// round 14
// speedup vs baseline: 1.1692x; 1.1692x over previous
#include <cuda_runtime.h>
#include <cuda_fp16.h>
#include <math.h>
#include <stdint.h>

// Problem constants
#define BB   2
#define SS   2048
#define EE   2048
#define HH   16
#define DD   128
#define MTOT (BB*SS)      // 4096
#define NQKV (3*EE)       // 6144
#define KDIM EE           // 2048

// ---------------------------------------------------------------------------
// Scratch (device globals; no allocation allowed)
// ---------------------------------------------------------------------------
__device__ float g_q[(size_t)BB*HH*SS*DD];     // fp32 (pre-RoPE)
__device__ float g_k[(size_t)BB*HH*SS*DD];
__device__ float g_cos[SS*64];
__device__ float g_sin[SS*64];

__device__ __half g_qh[(size_t)BB*HH*SS*DD];   // RoPE'd Q hi
__device__ __half g_ql[(size_t)BB*HH*SS*DD];   // RoPE'd Q lo
__device__ __half g_kh[(size_t)BB*HH*SS*DD];   // RoPE'd K (single-rounded)
__device__ __half g_vh[(size_t)BB*HH*SS*DD];   // V (single-rounded)

__device__ __half g_xh[(size_t)MTOT*KDIM];     // x hi
__device__ __half g_xl[(size_t)MTOT*KDIM];     // x lo
__device__ __half g_wqh[(size_t)NQKV*KDIM];    // Wqkv (single-rounded)
__device__ __half g_owh[(size_t)EE*KDIM];      // out_w (single-rounded)
__device__ __half g_ch[(size_t)MTOT*EE];       // ctx hi
__device__ __half g_cl[(size_t)MTOT*EE];       // ctx lo

// ---------------------------------------------------------------------------
// Baseline-PTX helpers (sm_80+)
// ---------------------------------------------------------------------------
__device__ __forceinline__ uint32_t smem_u32(const void* p) {
    uint32_t a;
    asm("{ .reg .u64 t; cvta.to.shared.u64 t, %1; cvt.u32.u64 %0, t; }"
        : "=r"(a) : "l"(p));
    return a;
}

#define CP_ASYNC16(dst, src) \
    asm volatile("cp.async.cg.shared.global [%0], [%1], 16;" \
                 :: "r"(dst), "l"(src) : "memory")
#define CP_COMMIT() asm volatile("cp.async.commit_group;" ::: "memory")

__device__ __forceinline__ void ldmatrix_x4(uint32_t* r, uint32_t addr) {
    asm volatile("ldmatrix.sync.aligned.m8n8.x4.shared.b16 {%0,%1,%2,%3}, [%4];"
                 : "=r"(r[0]), "=r"(r[1]), "=r"(r[2]), "=r"(r[3]) : "r"(addr));
}
__device__ __forceinline__ void ldmatrix_x4_t(uint32_t* r, uint32_t addr) {
    asm volatile("ldmatrix.sync.aligned.m8n8.x4.trans.shared.b16 {%0,%1,%2,%3}, [%4];"
                 : "=r"(r[0]), "=r"(r[1]), "=r"(r[2]), "=r"(r[3]) : "r"(addr));
}

// fp16 inputs, fp32 accumulate
__device__ __forceinline__ void mma16816(float* c,
    uint32_t a0, uint32_t a1, uint32_t a2, uint32_t a3, uint32_t b0, uint32_t b1)
{
    asm volatile(
        "mma.sync.aligned.m16n8k16.row.col.f32.f16.f16.f32 "
        "{%0,%1,%2,%3}, {%4,%5,%6,%7}, {%8,%9}, {%0,%1,%2,%3};"
        : "+f"(c[0]), "+f"(c[1]), "+f"(c[2]), "+f"(c[3])
        : "r"(a0), "r"(a1), "r"(a2), "r"(a3), "r"(b0), "r"(b1));
}

__device__ __forceinline__ void split1(float x, __half& h, __half& l) {
    h = __float2half_rn(x);
    l = __float2half_rn(x - __half2float(h));
}
__device__ __forceinline__ uint32_t pack_h2(float x, float y) {
    __half2 hp = __floats2half2_rn(x, y);
    return *(uint32_t*)&hp;
}

// ---------------------------------------------------------------------------
// fp32 -> (hi, lo) fp16 split (bulk) and hi-only convert
// ---------------------------------------------------------------------------
__global__ void split_kernel(const float* __restrict__ src,
                             __half* __restrict__ hi,
                             __half* __restrict__ lo, int n)
{
    int i4 = (blockIdx.x * blockDim.x + threadIdx.x) << 2;
    if (i4 >= n) return;
    float4 v = *(const float4*)(src + i4);
    float xs[4] = {v.x, v.y, v.z, v.w};
    __half h[4], l[4];
#pragma unroll
    for (int q = 0; q < 4; q++) split1(xs[q], h[q], l[q]);
    *(uint2*)(hi + i4) = *(uint2*)h;
    *(uint2*)(lo + i4) = *(uint2*)l;
}

__global__ void cvt_hi_kernel(const float* __restrict__ src,
                              __half* __restrict__ hi, int n)
{
    int i4 = (blockIdx.x * blockDim.x + threadIdx.x) << 2;
    if (i4 >= n) return;
    float4 v = *(const float4*)(src + i4);
    __half h[4];
    h[0] = __float2half_rn(v.x); h[1] = __float2half_rn(v.y);
    h[2] = __float2half_rn(v.z); h[3] = __float2half_rn(v.w);
    *(uint2*)(hi + i4) = *(uint2*)h;
}

// ---------------------------------------------------------------------------
// RoPE table
// ---------------------------------------------------------------------------
__global__ void rope_table_kernel()
{
    int idx = blockIdx.x * blockDim.x + threadIdx.x;
    if (idx >= SS * 64) return;
    int j = idx & 63;
    int s = idx >> 6;
    double denom = pow(10000.0, ((double)(2 * j)) / 128.0);
    float invf = (float)(1.0 / denom);
    float ph = (float)s * invf;
    double p = (double)ph;
    g_cos[idx] = (float)cos(p);
    g_sin[idx] = (float)sin(p);
}

// RoPE on fp32 q/k. Q -> (hi, lo) fp16 split; K -> single-rounded fp16.
__global__ void rope_split_kernel()
{
    int idx = blockIdx.x * blockDim.x + threadIdx.x;   // 2*65536*64
    int j      = idx & 63;
    int r      = idx >> 6;
    int bhs    = r & (BB*HH*SS - 1);
    int tensor = r >> 16;
    int s      = bhs & (SS - 1);

    size_t base = (size_t)bhs * DD;
    float c  = g_cos[(s << 6) + j];
    float sn = g_sin[(s << 6) + j];
    if (tensor == 0) {
        float x1 = g_q[base + j];
        float x2 = g_q[base + j + 64];
        float y1 = x1 * c - x2 * sn;
        float y2 = x2 * c + x1 * sn;
        __half h, l;
        split1(y1, h, l); g_qh[base + j] = h;      g_ql[base + j] = l;
        split1(y2, h, l); g_qh[base + j + 64] = h; g_ql[base + j + 64] = l;
    } else {
        float x1 = g_k[base + j];
        float x2 = g_k[base + j + 64];
        float y1 = x1 * c - x2 * sn;
        float y2 = x2 * c + x1 * sn;
        g_kh[base + j]      = __float2half_rn(y1);
        g_kh[base + j + 64] = __float2half_rn(y2);
    }
}

// ---------------------------------------------------------------------------
// mma.sync fp16x2 GEMM: C = Ah*Bh + Al*Bh + bias  (A split, B single-rounded)
// Tile: CTA 128x128, warp 64x32, K-chunk 32, 3-stage cp.async pipeline
// (R8-proven schedule). __launch_bounds__(256, 2): cap regs at 128 so TWO
// CTAs co-reside per SM (2 x 92160 B smem = 184 KB < 228 KB) -> 4 warps/SMSP
// for latency hiding. MODE 0: q,k fp32 + v fp16. MODE 1: C fp32.
// ---------------------------------------------------------------------------
#define GK_CHUNK   32
#define TILE_BYTES 10240            // 128 rows * 80B (32 fp16 + 8 pad)
#define STAGE_BYTES (3*TILE_BYTES)  // Ah, Al, Bh
#define GSTAGES    3
#define GEMM_SMEM  (GSTAGES*STAGE_BYTES)   // 92160 B

__device__ __forceinline__ void gemm_load_stage(
    uint32_t stg, const __half* const* tp, int K, int kt, int tid)
{
#pragma unroll
    for (int t = 0; t < 3; t++) {
        const __half* p = tp[t];
#pragma unroll
        for (int i = 0; i < 2; i++) {
            int slot = tid + (i << 8);
            int row  = slot >> 2;
            int c    = slot & 3;
            uint32_t dst = stg + t * TILE_BYTES + row * 80 + c * 16;
            const void* src = p + (size_t)row * K + kt + c * 8;
            CP_ASYNC16(dst, src);
        }
    }
    CP_COMMIT();
}

template<int MODE>
__global__ __launch_bounds__(256, 2) void gemm_mma(
    const __half* __restrict__ Ah, const __half* __restrict__ Al,
    const __half* __restrict__ Bh,
    const float* __restrict__ bias, float* __restrict__ C,
    int M, int N, int K)
{
    extern __shared__ char smch[];
    const uint32_t sbase = smem_u32(smch);
    const int tid  = threadIdx.x;
    const int wid  = tid >> 5;
    const int lane = tid & 31;
    const int wm   = wid & 1;
    const int wn   = wid >> 1;
    const int m0   = blockIdx.y << 7;
    const int n0   = blockIdx.x << 7;

    const __half* tp[3] = {
        Ah + (size_t)m0 * K, Al + (size_t)m0 * K, Bh + (size_t)n0 * K };

    float c[4][4][4];
#pragma unroll
    for (int i = 0; i < 4; i++)
#pragma unroll
        for (int j = 0; j < 4; j++)
#pragma unroll
            for (int q = 0; q < 4; q++) c[i][j][q] = 0.f;

    const int T = K / GK_CHUNK;

    gemm_load_stage(sbase + 0 * STAGE_BYTES, tp, K, 0 * GK_CHUNK, tid);
    gemm_load_stage(sbase + 1 * STAGE_BYTES, tp, K, 1 * GK_CHUNK, tid);
    gemm_load_stage(sbase + 2 * STAGE_BYTES, tp, K, 2 * GK_CHUNK, tid);

    const int rsel = lane & 15;
    const int csel = (lane >> 4) << 3;

#pragma unroll 1
    for (int t = 0; t < T; t++) {
        int rem = (T - 1) - t;
        if (rem >= 2)      asm volatile("cp.async.wait_group 2;" ::: "memory");
        else if (rem == 1) asm volatile("cp.async.wait_group 1;" ::: "memory");
        else               asm volatile("cp.async.wait_group 0;" ::: "memory");
        __syncthreads();

        const uint32_t stg = sbase + (t % GSTAGES) * STAGE_BYTES;
        const uint32_t aAh = stg;
        const uint32_t aAl = stg + TILE_BYTES;
        const uint32_t aB  = stg + 2*TILE_BYTES;

#pragma unroll
        for (int k16 = 0; k16 < 2; k16++) {
            const int koff = (csel + k16*16)*2;
            uint32_t a0[4][4], a1[4][4], b[2][4];
#pragma unroll
            for (int i = 0; i < 4; i++) {
                ldmatrix_x4(a0[i], aAh + (wm*64 + i*16 + rsel)*80 + koff);
                ldmatrix_x4(a1[i], aAl + (wm*64 + i*16 + rsel)*80 + koff);
            }
#pragma unroll
            for (int j16 = 0; j16 < 2; j16++)
                ldmatrix_x4(b[j16], aB + (wn*32 + j16*16 + rsel)*80 + koff);
#pragma unroll
            for (int i = 0; i < 4; i++)
#pragma unroll
                for (int j16 = 0; j16 < 2; j16++) {
                    mma16816(c[i][j16*2+0], a0[i][0], a0[i][1], a0[i][2], a0[i][3],
                             b[j16][0], b[j16][2]);
                    mma16816(c[i][j16*2+1], a0[i][0], a0[i][1], a0[i][2], a0[i][3],
                             b[j16][1], b[j16][3]);
                }
#pragma unroll
            for (int i = 0; i < 4; i++)
#pragma unroll
                for (int j16 = 0; j16 < 2; j16++) {
                    mma16816(c[i][j16*2+0], a1[i][0], a1[i][1], a1[i][2], a1[i][3],
                             b[j16][0], b[j16][2]);
                    mma16816(c[i][j16*2+1], a1[i][0], a1[i][1], a1[i][2], a1[i][3],
                             b[j16][1], b[j16][3]);
                }
        }
        __syncthreads();
        if (t + 3 < T)
            gemm_load_stage(sbase + ((t+3) % GSTAGES) * STAGE_BYTES,
                            tp, K, (t+3) * GK_CHUNK, tid);
    }

#pragma unroll
    for (int i = 0; i < 4; i++) {
        int rowA = m0 + wm*64 + i*16 + (lane >> 2);
#pragma unroll
        for (int j = 0; j < 4; j++) {
            int col = n0 + wn*32 + j*8 + (lane & 3)*2;
            float b0 = bias[col], b1 = bias[col+1];
            float2 lo2 = make_float2(c[i][j][0] + b0, c[i][j][1] + b1);
            float2 hi2 = make_float2(c[i][j][2] + b0, c[i][j][3] + b1);
#pragma unroll
            for (int half = 0; half < 2; half++) {
                int row = rowA + half*8;
                float2 v = half ? hi2 : lo2;
                if (MODE == 0) {
                    int which = col >> 11;
                    int h = (col >> 7) & (HH - 1);
                    int d = col & (DD - 1);
                    int bb = row >> 11;
                    int s = row & (SS - 1);
                    size_t off = (((size_t)bb * HH + h) * SS + s) * DD + d;
                    if (which == 2) {
                        __half2 hp = __halves2half2(__float2half_rn(v.x),
                                                    __float2half_rn(v.y));
                        *(__half2*)&g_vh[off] = hp;
                    } else {
                        float* dst = which ? g_k : g_q;
                        *(float2*)&dst[off] = v;
                    }
                } else {
                    *(float2*)&C[(size_t)row * N + col] = v;
                }
            }
        }
    }
}

// ---------------------------------------------------------------------------
// Tensor-core flash attention, fp16:
//   S = Qh*Kh + Ql*Kh  (Q split, K single-rounded)
//   O += Ph*Vh         (P single-rounded — Pl product dropped this round)
// CTA = 128 q rows x (b,h). 8 warps x 16 q rows. 64-key K/V tiles,
// single-buffered, split-phase pipelined (R6/R8-verified schedule).
// ---------------------------------------------------------------------------
#define AT_ROWB  272                    // 128 fp16 + 8 pad
#define Q_BYTES  (128*AT_ROWB)          // 34816
#define KV_TILE  (64*AT_ROWB)           // 17408
#define ATT_SMEM (2*Q_BYTES + 2*KV_TILE)  // 104448

__global__ __launch_bounds__(256, 1) void attn_mma_kernel()
{
    extern __shared__ char smc[];
    const uint32_t sb  = smem_u32(smc);
    const uint32_t sQh = sb;
    const uint32_t sQl = sb + Q_BYTES;
    const uint32_t sKh = sb + 2*Q_BYTES;
    const uint32_t sVh = sKh + KV_TILE;

    const int tid  = threadIdx.x;
    const int wid  = tid >> 5;
    const int lane = tid & 31;
    const int q0 = blockIdx.x << 7;
    const int h  = blockIdx.y;
    const int b  = blockIdx.z;

    const size_t head_off = ((size_t)b * HH + h) * SS * DD;
    const __half* Qhg = g_qh + head_off + (size_t)q0 * DD;
    const __half* Qlg = g_ql + head_off + (size_t)q0 * DD;
    const __half* Khg = g_kh + head_off;
    const __half* Vhg = g_vh + head_off;

    auto load_k = [&](int kt) {
#pragma unroll
        for (int i = 0; i < 4; i++) {
            int idx = tid + (i << 8);          // 0..1023
            int row = idx >> 4, c = idx & 15;
            CP_ASYNC16(sKh + row*AT_ROWB + c*16, Khg + (size_t)(kt+row)*DD + c*8);
        }
        CP_COMMIT();
    };
    auto load_v = [&](int kt) {
#pragma unroll
        for (int i = 0; i < 4; i++) {
            int idx = tid + (i << 8);
            int row = idx >> 4, c = idx & 15;
            CP_ASYNC16(sVh + row*AT_ROWB + c*16, Vhg + (size_t)(kt+row)*DD + c*8);
        }
        CP_COMMIT();
    };

    // ---- prologue: Q (hi+lo) + K0 + V0, one commit group ----
    {
#pragma unroll
        for (int i = 0; i < 8; i++) {
            int cidx = tid + (i << 8);         // 0..2047
            int row = cidx >> 4, c = cidx & 15;
            CP_ASYNC16(sQh + row*AT_ROWB + c*16, Qhg + (size_t)row*DD + c*8);
            CP_ASYNC16(sQl + row*AT_ROWB + c*16, Qlg + (size_t)row*DD + c*8);
        }
#pragma unroll
        for (int i = 0; i < 8; i++) {
            int idx = tid + (i << 8);          // 0..2047: Kh, Vh tiles
            int arr = idx >> 10;               // 0..1
            int row = (idx >> 4) & 63;
            int c   = idx & 15;
            const __half* src = arr ? Vhg : Khg;
            uint32_t dstb = arr ? sVh : sKh;
            CP_ASYNC16(dstb + row*AT_ROWB + c*16, src + (size_t)row*DD + c*8);
        }
        CP_COMMIT();
    }

    float o[16][4];
#pragma unroll
    for (int n = 0; n < 16; n++)
#pragma unroll
        for (int q = 0; q < 4; q++) o[n][q] = 0.f;
    float m0 = -1e30f, m1 = -1e30f, l0 = 0.f, l1 = 0.f;

    const float scale = 0.088388347648318447f;   // 1/sqrt(128)
    const int wq = wid << 4;
    const int rsel = lane & 15;
    const int csel = (lane >> 4) << 3;
    const int NT = SS / 64;                      // 32

#pragma unroll 1
    for (int t = 0; t < NT; t++) {
        // ---- K(t) ready? ----
        if (t == 0) asm volatile("cp.async.wait_group 0;" ::: "memory");
        else        asm volatile("cp.async.wait_group 1;" ::: "memory");
        __syncthreads();

        // ---- scores S = Qh*Kh + Ql*Kh ----
        float S[8][4];
#pragma unroll
        for (int j = 0; j < 8; j++)
#pragma unroll
            for (int q = 0; q < 4; q++) S[j][q] = 0.f;

#pragma unroll
        for (int ds = 0; ds < 8; ds++) {
            const int doff = (ds*16 + csel) * 2;
            uint32_t qh[4], ql[4], kh[4][4];
            ldmatrix_x4(qh, sQh + (wq + rsel)*AT_ROWB + doff);
            ldmatrix_x4(ql, sQl + (wq + rsel)*AT_ROWB + doff);
#pragma unroll
            for (int j16 = 0; j16 < 4; j16++)
                ldmatrix_x4(kh[j16], sKh + (j16*16 + rsel)*AT_ROWB + doff);
#pragma unroll
            for (int j16 = 0; j16 < 4; j16++) {
                mma16816(S[2*j16],   qh[0], qh[1], qh[2], qh[3], kh[j16][0], kh[j16][2]);
                mma16816(S[2*j16+1], qh[0], qh[1], qh[2], qh[3], kh[j16][1], kh[j16][3]);
            }
#pragma unroll
            for (int j16 = 0; j16 < 4; j16++) {
                mma16816(S[2*j16],   ql[0], ql[1], ql[2], ql[3], kh[j16][0], kh[j16][2]);
                mma16816(S[2*j16+1], ql[0], ql[1], ql[2], ql[3], kh[j16][1], kh[j16][3]);
            }
        }
        __syncthreads();                 // all warps done reading K tile

        if (t + 1 < NT) load_k((t + 1) << 6);

        // ---- online softmax ----
        float mx0 = -1e30f, mx1 = -1e30f;
#pragma unroll
        for (int j = 0; j < 8; j++) {
            S[j][0] *= scale; S[j][1] *= scale;
            S[j][2] *= scale; S[j][3] *= scale;
            mx0 = fmaxf(mx0, fmaxf(S[j][0], S[j][1]));
            mx1 = fmaxf(mx1, fmaxf(S[j][2], S[j][3]));
        }
        mx0 = fmaxf(mx0, __shfl_xor_sync(0xffffffffu, mx0, 1));
        mx0 = fmaxf(mx0, __shfl_xor_sync(0xffffffffu, mx0, 2));
        mx1 = fmaxf(mx1, __shfl_xor_sync(0xffffffffu, mx1, 1));
        mx1 = fmaxf(mx1, __shfl_xor_sync(0xffffffffu, mx1, 2));

        float mn0 = fmaxf(m0, mx0), mn1 = fmaxf(m1, mx1);
        float fac0 = __expf(m0 - mn0), fac1 = __expf(m1 - mn1);
        float rs0 = 0.f, rs1 = 0.f;
#pragma unroll
        for (int j = 0; j < 8; j++) {
            S[j][0] = __expf(S[j][0] - mn0); rs0 += S[j][0];
            S[j][1] = __expf(S[j][1] - mn0); rs0 += S[j][1];
            S[j][2] = __expf(S[j][2] - mn1); rs1 += S[j][2];
            S[j][3] = __expf(S[j][3] - mn1); rs1 += S[j][3];
        }
        rs0 += __shfl_xor_sync(0xffffffffu, rs0, 1);
        rs0 += __shfl_xor_sync(0xffffffffu, rs0, 2);
        rs1 += __shfl_xor_sync(0xffffffffu, rs1, 1);
        rs1 += __shfl_xor_sync(0xffffffffu, rs1, 2);
        l0 = l0 * fac0 + rs0; m0 = mn0;
        l1 = l1 * fac1 + rs1; m1 = mn1;
#pragma unroll
        for (int n = 0; n < 16; n++) {
            o[n][0] *= fac0; o[n][1] *= fac0;
            o[n][2] *= fac1; o[n][3] *= fac1;
        }

        // ---- V(t) ready? ----
        if (t + 1 < NT) asm volatile("cp.async.wait_group 1;" ::: "memory");
        else            asm volatile("cp.async.wait_group 0;" ::: "memory");
        __syncthreads();

        // ---- O += Ph*Vh (single product; Pl dropped) ----
#pragma unroll
        for (int kk = 0; kk < 4; kk++) {
            uint32_t ah[4];
            ah[0] = pack_h2(S[2*kk][0],   S[2*kk][1]);
            ah[1] = pack_h2(S[2*kk][2],   S[2*kk][3]);
            ah[2] = pack_h2(S[2*kk+1][0], S[2*kk+1][1]);
            ah[3] = pack_h2(S[2*kk+1][2], S[2*kk+1][3]);
            const uint32_t vrow = (kk*16 + rsel)*AT_ROWB;
#pragma unroll
            for (int db = 0; db < 8; db += 2) {
                uint32_t vh[2][4];
                ldmatrix_x4_t(vh[0], sVh + vrow + (db*16 + csel)*2);
                ldmatrix_x4_t(vh[1], sVh + vrow + ((db+1)*16 + csel)*2);
#pragma unroll
                for (int u = 0; u < 2; u++) {
                    int n = (db+u)*2;
                    mma16816(o[n],   ah[0], ah[1], ah[2], ah[3], vh[u][0], vh[u][1]);
                    mma16816(o[n+1], ah[0], ah[1], ah[2], ah[3], vh[u][2], vh[u][3]);
                }
            }
        }
        __syncthreads();                 // all warps done reading V tile

        if (t + 1 < NT) load_v((t + 1) << 6);
    }

    // ---- epilogue: normalize, split to hi/lo fp16, write ctx ----
    const int g  = lane >> 2;
    const int tg = lane & 3;
    const float inv0 = 1.f / l0;
    const float inv1 = 1.f / l1;
    const int s0 = q0 + wq + g;
    const int s1 = s0 + 8;
#pragma unroll
    for (int n = 0; n < 16; n++) {
        int col = h*DD + 8*n + 2*tg;
        {
            size_t off = (size_t)(b*SS + s0) * EE + col;
            __half h0, l0b, h1, l1b;
            split1(o[n][0] * inv0, h0, l0b);
            split1(o[n][1] * inv0, h1, l1b);
            *(__half2*)&g_ch[off] = __halves2half2(h0, h1);
            *(__half2*)&g_cl[off] = __halves2half2(l0b, l1b);
        }
        {
            size_t off = (size_t)(b*SS + s1) * EE + col;
            __half h0, l0b, h1, l1b;
            split1(o[n][2] * inv1, h0, l0b);
            split1(o[n][3] * inv1, h1, l1b);
            *(__half2*)&g_ch[off] = __halves2half2(h0, h1);
            *(__half2*)&g_cl[off] = __halves2half2(l0b, l1b);
        }
    }
}

// ---------------------------------------------------------------------------
// Launch
// ---------------------------------------------------------------------------
extern "C" void kernel_launch(void* const* d_in, const int* in_sizes, int n_in,
                              void* d_out, int out_size)
{
    (void)in_sizes; (void)n_in; (void)out_size;
    const float* x      = (const float*)d_in[0];
    const float* Wqkv_w = (const float*)d_in[1];
    const float* Wqkv_b = (const float*)d_in[2];
    const float* out_w  = (const float*)d_in[3];
    const float* out_b  = (const float*)d_in[4];
    float* out = (float*)d_out;

    __half *xh, *xl, *wqh, *owh, *ch, *cl;
    cudaGetSymbolAddress((void**)&xh,  g_xh);
    cudaGetSymbolAddress((void**)&xl,  g_xl);
    cudaGetSymbolAddress((void**)&wqh, g_wqh);
    cudaGetSymbolAddress((void**)&owh, g_owh);
    cudaGetSymbolAddress((void**)&ch,  g_ch);
    cudaGetSymbolAddress((void**)&cl,  g_cl);

    cudaFuncSetAttribute(attn_mma_kernel, cudaFuncAttributeMaxDynamicSharedMemorySize,
                         ATT_SMEM);
    cudaFuncSetAttribute(gemm_mma<0>, cudaFuncAttributeMaxDynamicSharedMemorySize,
                         GEMM_SMEM);
    cudaFuncSetAttribute(gemm_mma<1>, cudaFuncAttributeMaxDynamicSharedMemorySize,
                         GEMM_SMEM);

    rope_table_kernel<<<(SS * 64 + 255) / 256, 256>>>();

    split_kernel<<<(MTOT*KDIM/4 + 255) / 256, 256>>>(x, xh, xl, MTOT*KDIM);
    cvt_hi_kernel<<<(NQKV*KDIM/4 + 255) / 256, 256>>>(Wqkv_w, wqh, NQKV*KDIM);
    cvt_hi_kernel<<<(EE*KDIM/4 + 255) / 256, 256>>>(out_w, owh, EE*KDIM);

    gemm_mma<0><<<dim3(NQKV/128, MTOT/128), 256, GEMM_SMEM>>>(
        xh, xl, wqh, Wqkv_b, nullptr, MTOT, NQKV, KDIM);

    rope_split_kernel<<<(2 * BB * HH * SS * 64) / 256, 256>>>();

    attn_mma_kernel<<<dim3(SS/128, HH, BB), 256, ATT_SMEM>>>();

    gemm_mma<1><<<dim3(EE/128, MTOT/128), 256, GEMM_SMEM>>>(
        ch, cl, owh, out_b, out, MTOT, EE, KDIM);
}

// round 15
// speedup vs baseline: 1.4672x; 1.2549x over previous
#include <cuda_runtime.h>
#include <cuda_fp16.h>
#include <math.h>
#include <stdint.h>

// Problem constants
#define BB   2
#define SS   2048
#define EE   2048
#define HH   16
#define DD   128
#define MTOT (BB*SS)      // 4096
#define NQKV (3*EE)       // 6144
#define KDIM EE           // 2048

// ---------------------------------------------------------------------------
// Scratch (device globals; no allocation allowed)
// ---------------------------------------------------------------------------
__device__ float g_q[(size_t)BB*HH*SS*DD];     // fp32 (pre-RoPE)
__device__ float g_k[(size_t)BB*HH*SS*DD];
__device__ float g_cos[SS*64];
__device__ float g_sin[SS*64];

__device__ __half g_qh[(size_t)BB*HH*SS*DD];   // RoPE'd Q hi
__device__ __half g_ql[(size_t)BB*HH*SS*DD];   // RoPE'd Q lo
__device__ __half g_kh[(size_t)BB*HH*SS*DD];   // RoPE'd K (single-rounded)
__device__ __half g_vh[(size_t)BB*HH*SS*DD];   // V (single-rounded)

__device__ __half g_xh[(size_t)MTOT*KDIM];     // x (single-rounded this round)
__device__ __half g_wqh[(size_t)NQKV*KDIM];    // Wqkv (single-rounded)
__device__ __half g_owh[(size_t)EE*KDIM];      // out_w (single-rounded)
__device__ __half g_ch[(size_t)MTOT*EE];       // ctx hi
__device__ __half g_cl[(size_t)MTOT*EE];       // ctx lo

// ---------------------------------------------------------------------------
// Baseline-PTX helpers (sm_80+)
// ---------------------------------------------------------------------------
__device__ __forceinline__ uint32_t smem_u32(const void* p) {
    uint32_t a;
    asm("{ .reg .u64 t; cvta.to.shared.u64 t, %1; cvt.u32.u64 %0, t; }"
        : "=r"(a) : "l"(p));
    return a;
}

#define CP_ASYNC16(dst, src) \
    asm volatile("cp.async.cg.shared.global [%0], [%1], 16;" \
                 :: "r"(dst), "l"(src) : "memory")
#define CP_COMMIT() asm volatile("cp.async.commit_group;" ::: "memory")

__device__ __forceinline__ void ldmatrix_x4(uint32_t* r, uint32_t addr) {
    asm volatile("ldmatrix.sync.aligned.m8n8.x4.shared.b16 {%0,%1,%2,%3}, [%4];"
                 : "=r"(r[0]), "=r"(r[1]), "=r"(r[2]), "=r"(r[3]) : "r"(addr));
}
__device__ __forceinline__ void ldmatrix_x4_t(uint32_t* r, uint32_t addr) {
    asm volatile("ldmatrix.sync.aligned.m8n8.x4.trans.shared.b16 {%0,%1,%2,%3}, [%4];"
                 : "=r"(r[0]), "=r"(r[1]), "=r"(r[2]), "=r"(r[3]) : "r"(addr));
}

// fp16 inputs, fp32 accumulate
__device__ __forceinline__ void mma16816(float* c,
    uint32_t a0, uint32_t a1, uint32_t a2, uint32_t a3, uint32_t b0, uint32_t b1)
{
    asm volatile(
        "mma.sync.aligned.m16n8k16.row.col.f32.f16.f16.f32 "
        "{%0,%1,%2,%3}, {%4,%5,%6,%7}, {%8,%9}, {%0,%1,%2,%3};"
        : "+f"(c[0]), "+f"(c[1]), "+f"(c[2]), "+f"(c[3])
        : "r"(a0), "r"(a1), "r"(a2), "r"(a3), "r"(b0), "r"(b1));
}

__device__ __forceinline__ void split1(float x, __half& h, __half& l) {
    h = __float2half_rn(x);
    l = __float2half_rn(x - __half2float(h));
}
__device__ __forceinline__ uint32_t pack_h2(float x, float y) {
    __half2 hp = __floats2half2_rn(x, y);
    return *(uint32_t*)&hp;
}

// ---------------------------------------------------------------------------
// fp32 -> (hi, lo) fp16 split (bulk) and hi-only convert
// ---------------------------------------------------------------------------
__global__ void split_kernel(const float* __restrict__ src,
                             __half* __restrict__ hi,
                             __half* __restrict__ lo, int n)
{
    int i4 = (blockIdx.x * blockDim.x + threadIdx.x) << 2;
    if (i4 >= n) return;
    float4 v = *(const float4*)(src + i4);
    float xs[4] = {v.x, v.y, v.z, v.w};
    __half h[4], l[4];
#pragma unroll
    for (int q = 0; q < 4; q++) split1(xs[q], h[q], l[q]);
    *(uint2*)(hi + i4) = *(uint2*)h;
    *(uint2*)(lo + i4) = *(uint2*)l;
}

__global__ void cvt_hi_kernel(const float* __restrict__ src,
                              __half* __restrict__ hi, int n)
{
    int i4 = (blockIdx.x * blockDim.x + threadIdx.x) << 2;
    if (i4 >= n) return;
    float4 v = *(const float4*)(src + i4);
    __half h[4];
    h[0] = __float2half_rn(v.x); h[1] = __float2half_rn(v.y);
    h[2] = __float2half_rn(v.z); h[3] = __float2half_rn(v.w);
    *(uint2*)(hi + i4) = *(uint2*)h;
}

// ---------------------------------------------------------------------------
// RoPE table
// ---------------------------------------------------------------------------
__global__ void rope_table_kernel()
{
    int idx = blockIdx.x * blockDim.x + threadIdx.x;
    if (idx >= SS * 64) return;
    int j = idx & 63;
    int s = idx >> 6;
    double denom = pow(10000.0, ((double)(2 * j)) / 128.0);
    float invf = (float)(1.0 / denom);
    float ph = (float)s * invf;
    double p = (double)ph;
    g_cos[idx] = (float)cos(p);
    g_sin[idx] = (float)sin(p);
}

// RoPE on fp32 q/k. Q -> (hi, lo) fp16 split; K -> single-rounded fp16.
__global__ void rope_split_kernel()
{
    int idx = blockIdx.x * blockDim.x + threadIdx.x;   // 2*65536*64
    int j      = idx & 63;
    int r      = idx >> 6;
    int bhs    = r & (BB*HH*SS - 1);
    int tensor = r >> 16;
    int s      = bhs & (SS - 1);

    size_t base = (size_t)bhs * DD;
    float c  = g_cos[(s << 6) + j];
    float sn = g_sin[(s << 6) + j];
    if (tensor == 0) {
        float x1 = g_q[base + j];
        float x2 = g_q[base + j + 64];
        float y1 = x1 * c - x2 * sn;
        float y2 = x2 * c + x1 * sn;
        __half h, l;
        split1(y1, h, l); g_qh[base + j] = h;      g_ql[base + j] = l;
        split1(y2, h, l); g_qh[base + j + 64] = h; g_ql[base + j + 64] = l;
    } else {
        float x1 = g_k[base + j];
        float x2 = g_k[base + j + 64];
        float y1 = x1 * c - x2 * sn;
        float y2 = x2 * c + x1 * sn;
        g_kh[base + j]      = __float2half_rn(y1);
        g_kh[base + j + 64] = __float2half_rn(y2);
    }
}

// ---------------------------------------------------------------------------
// mma.sync fp16 GEMM, templated on NPA (number of A parts):
//   NPA=1: C = A*B + bias          (A single-rounded; QKV projection)
//   NPA=2: C = Ah*B + Al*B + bias  (A split; out projection)
// Tile: CTA 128x128, warp 64x32, K-chunk 32, 3-stage cp.async pipeline,
// __launch_bounds__(256, 2) (R14-passing config).
// MODE 0: q,k fp32 + v fp16. MODE 1: C fp32.
// ---------------------------------------------------------------------------
#define GK_CHUNK   32
#define TILE_BYTES 10240            // 128 rows * 80B (32 fp16 + 8 pad)
#define GSTAGES    3

template<int NT>
__device__ __forceinline__ void gemm_load_stage(
    uint32_t stg, const __half* const* tp, int K, int kt, int tid)
{
#pragma unroll
    for (int t = 0; t < NT; t++) {
        const __half* p = tp[t];
#pragma unroll
        for (int i = 0; i < 2; i++) {
            int slot = tid + (i << 8);
            int row  = slot >> 2;
            int c    = slot & 3;
            uint32_t dst = stg + t * TILE_BYTES + row * 80 + c * 16;
            const void* src = p + (size_t)row * K + kt + c * 8;
            CP_ASYNC16(dst, src);
        }
    }
    CP_COMMIT();
}

template<int MODE, int NPA>
__global__ __launch_bounds__(256, 2) void gemm_mma(
    const __half* __restrict__ Ah, const __half* __restrict__ Al,
    const __half* __restrict__ Bh,
    const float* __restrict__ bias, float* __restrict__ C,
    int M, int N, int K)
{
    constexpr int NTILES = NPA + 1;
    constexpr uint32_t STAGE_B = NTILES * TILE_BYTES;

    extern __shared__ char smch[];
    const uint32_t sbase = smem_u32(smch);
    const int tid  = threadIdx.x;
    const int wid  = tid >> 5;
    const int lane = tid & 31;
    const int wm   = wid & 1;
    const int wn   = wid >> 1;
    const int m0   = blockIdx.y << 7;
    const int n0   = blockIdx.x << 7;

    const __half* tp[NTILES];
    tp[0] = Ah + (size_t)m0 * K;
    if (NPA == 2) tp[1] = Al + (size_t)m0 * K;
    tp[NTILES - 1] = Bh + (size_t)n0 * K;

    float c[4][4][4];
#pragma unroll
    for (int i = 0; i < 4; i++)
#pragma unroll
        for (int j = 0; j < 4; j++)
#pragma unroll
            for (int q = 0; q < 4; q++) c[i][j][q] = 0.f;

    const int T = K / GK_CHUNK;

    gemm_load_stage<NTILES>(sbase + 0 * STAGE_B, tp, K, 0 * GK_CHUNK, tid);
    gemm_load_stage<NTILES>(sbase + 1 * STAGE_B, tp, K, 1 * GK_CHUNK, tid);
    gemm_load_stage<NTILES>(sbase + 2 * STAGE_B, tp, K, 2 * GK_CHUNK, tid);

    const int rsel = lane & 15;
    const int csel = (lane >> 4) << 3;

#pragma unroll 1
    for (int t = 0; t < T; t++) {
        int rem = (T - 1) - t;
        if (rem >= 2)      asm volatile("cp.async.wait_group 2;" ::: "memory");
        else if (rem == 1) asm volatile("cp.async.wait_group 1;" ::: "memory");
        else               asm volatile("cp.async.wait_group 0;" ::: "memory");
        __syncthreads();

        const uint32_t stg = sbase + (t % GSTAGES) * STAGE_B;
        const uint32_t aAh = stg;
        const uint32_t aAl = stg + TILE_BYTES;            // valid when NPA==2
        const uint32_t aB  = stg + NPA * TILE_BYTES;

#pragma unroll
        for (int k16 = 0; k16 < 2; k16++) {
            const int koff = (csel + k16*16)*2;
            uint32_t a0[4][4], b[2][4];
#pragma unroll
            for (int i = 0; i < 4; i++)
                ldmatrix_x4(a0[i], aAh + (wm*64 + i*16 + rsel)*80 + koff);
#pragma unroll
            for (int j16 = 0; j16 < 2; j16++)
                ldmatrix_x4(b[j16], aB + (wn*32 + j16*16 + rsel)*80 + koff);
#pragma unroll
            for (int i = 0; i < 4; i++)
#pragma unroll
                for (int j16 = 0; j16 < 2; j16++) {
                    mma16816(c[i][j16*2+0], a0[i][0], a0[i][1], a0[i][2], a0[i][3],
                             b[j16][0], b[j16][2]);
                    mma16816(c[i][j16*2+1], a0[i][0], a0[i][1], a0[i][2], a0[i][3],
                             b[j16][1], b[j16][3]);
                }
            if (NPA == 2) {
                uint32_t a1[4][4];
#pragma unroll
                for (int i = 0; i < 4; i++)
                    ldmatrix_x4(a1[i], aAl + (wm*64 + i*16 + rsel)*80 + koff);
#pragma unroll
                for (int i = 0; i < 4; i++)
#pragma unroll
                    for (int j16 = 0; j16 < 2; j16++) {
                        mma16816(c[i][j16*2+0], a1[i][0], a1[i][1], a1[i][2], a1[i][3],
                                 b[j16][0], b[j16][2]);
                        mma16816(c[i][j16*2+1], a1[i][0], a1[i][1], a1[i][2], a1[i][3],
                                 b[j16][1], b[j16][3]);
                    }
            }
        }
        __syncthreads();
        if (t + 3 < T)
            gemm_load_stage<NTILES>(sbase + ((t+3) % GSTAGES) * STAGE_B,
                                    tp, K, (t+3) * GK_CHUNK, tid);
    }

#pragma unroll
    for (int i = 0; i < 4; i++) {
        int rowA = m0 + wm*64 + i*16 + (lane >> 2);
#pragma unroll
        for (int j = 0; j < 4; j++) {
            int col = n0 + wn*32 + j*8 + (lane & 3)*2;
            float b0 = bias[col], b1 = bias[col+1];
            float2 lo2 = make_float2(c[i][j][0] + b0, c[i][j][1] + b1);
            float2 hi2 = make_float2(c[i][j][2] + b0, c[i][j][3] + b1);
#pragma unroll
            for (int half = 0; half < 2; half++) {
                int row = rowA + half*8;
                float2 v = half ? hi2 : lo2;
                if (MODE == 0) {
                    int which = col >> 11;
                    int h = (col >> 7) & (HH - 1);
                    int d = col & (DD - 1);
                    int bb = row >> 11;
                    int s = row & (SS - 1);
                    size_t off = (((size_t)bb * HH + h) * SS + s) * DD + d;
                    if (which == 2) {
                        __half2 hp = __halves2half2(__float2half_rn(v.x),
                                                    __float2half_rn(v.y));
                        *(__half2*)&g_vh[off] = hp;
                    } else {
                        float* dst = which ? g_k : g_q;
                        *(float2*)&dst[off] = v;
                    }
                } else {
                    *(float2*)&C[(size_t)row * N + col] = v;
                }
            }
        }
    }
}

// ---------------------------------------------------------------------------
// Tensor-core flash attention, fp16 (unchanged from R14 pass):
//   S = Qh*Kh + Ql*Kh  (Q split, K single-rounded)
//   O += Ph*Vh         (P single-rounded)
// ---------------------------------------------------------------------------
#define AT_ROWB  272                    // 128 fp16 + 8 pad
#define Q_BYTES  (128*AT_ROWB)          // 34816
#define KV_TILE  (64*AT_ROWB)           // 17408
#define ATT_SMEM (2*Q_BYTES + 2*KV_TILE)  // 104448

__global__ __launch_bounds__(256, 1) void attn_mma_kernel()
{
    extern __shared__ char smc[];
    const uint32_t sb  = smem_u32(smc);
    const uint32_t sQh = sb;
    const uint32_t sQl = sb + Q_BYTES;
    const uint32_t sKh = sb + 2*Q_BYTES;
    const uint32_t sVh = sKh + KV_TILE;

    const int tid  = threadIdx.x;
    const int wid  = tid >> 5;
    const int lane = tid & 31;
    const int q0 = blockIdx.x << 7;
    const int h  = blockIdx.y;
    const int b  = blockIdx.z;

    const size_t head_off = ((size_t)b * HH + h) * SS * DD;
    const __half* Qhg = g_qh + head_off + (size_t)q0 * DD;
    const __half* Qlg = g_ql + head_off + (size_t)q0 * DD;
    const __half* Khg = g_kh + head_off;
    const __half* Vhg = g_vh + head_off;

    auto load_k = [&](int kt) {
#pragma unroll
        for (int i = 0; i < 4; i++) {
            int idx = tid + (i << 8);          // 0..1023
            int row = idx >> 4, c = idx & 15;
            CP_ASYNC16(sKh + row*AT_ROWB + c*16, Khg + (size_t)(kt+row)*DD + c*8);
        }
        CP_COMMIT();
    };
    auto load_v = [&](int kt) {
#pragma unroll
        for (int i = 0; i < 4; i++) {
            int idx = tid + (i << 8);
            int row = idx >> 4, c = idx & 15;
            CP_ASYNC16(sVh + row*AT_ROWB + c*16, Vhg + (size_t)(kt+row)*DD + c*8);
        }
        CP_COMMIT();
    };

    // ---- prologue: Q (hi+lo) + K0 + V0, one commit group ----
    {
#pragma unroll
        for (int i = 0; i < 8; i++) {
            int cidx = tid + (i << 8);         // 0..2047
            int row = cidx >> 4, c = cidx & 15;
            CP_ASYNC16(sQh + row*AT_ROWB + c*16, Qhg + (size_t)row*DD + c*8);
            CP_ASYNC16(sQl + row*AT_ROWB + c*16, Qlg + (size_t)row*DD + c*8);
        }
#pragma unroll
        for (int i = 0; i < 8; i++) {
            int idx = tid + (i << 8);          // 0..2047: Kh, Vh tiles
            int arr = idx >> 10;               // 0..1
            int row = (idx >> 4) & 63;
            int c   = idx & 15;
            const __half* src = arr ? Vhg : Khg;
            uint32_t dstb = arr ? sVh : sKh;
            CP_ASYNC16(dstb + row*AT_ROWB + c*16, src + (size_t)row*DD + c*8);
        }
        CP_COMMIT();
    }

    float o[16][4];
#pragma unroll
    for (int n = 0; n < 16; n++)
#pragma unroll
        for (int q = 0; q < 4; q++) o[n][q] = 0.f;
    float m0 = -1e30f, m1 = -1e30f, l0 = 0.f, l1 = 0.f;

    const float scale = 0.088388347648318447f;   // 1/sqrt(128)
    const int wq = wid << 4;
    const int rsel = lane & 15;
    const int csel = (lane >> 4) << 3;
    const int NT = SS / 64;                      // 32

#pragma unroll 1
    for (int t = 0; t < NT; t++) {
        // ---- K(t) ready? ----
        if (t == 0) asm volatile("cp.async.wait_group 0;" ::: "memory");
        else        asm volatile("cp.async.wait_group 1;" ::: "memory");
        __syncthreads();

        // ---- scores S = Qh*Kh + Ql*Kh ----
        float S[8][4];
#pragma unroll
        for (int j = 0; j < 8; j++)
#pragma unroll
            for (int q = 0; q < 4; q++) S[j][q] = 0.f;

#pragma unroll
        for (int ds = 0; ds < 8; ds++) {
            const int doff = (ds*16 + csel) * 2;
            uint32_t qh[4], ql[4], kh[4][4];
            ldmatrix_x4(qh, sQh + (wq + rsel)*AT_ROWB + doff);
            ldmatrix_x4(ql, sQl + (wq + rsel)*AT_ROWB + doff);
#pragma unroll
            for (int j16 = 0; j16 < 4; j16++)
                ldmatrix_x4(kh[j16], sKh + (j16*16 + rsel)*AT_ROWB + doff);
#pragma unroll
            for (int j16 = 0; j16 < 4; j16++) {
                mma16816(S[2*j16],   qh[0], qh[1], qh[2], qh[3], kh[j16][0], kh[j16][2]);
                mma16816(S[2*j16+1], qh[0], qh[1], qh[2], qh[3], kh[j16][1], kh[j16][3]);
            }
#pragma unroll
            for (int j16 = 0; j16 < 4; j16++) {
                mma16816(S[2*j16],   ql[0], ql[1], ql[2], ql[3], kh[j16][0], kh[j16][2]);
                mma16816(S[2*j16+1], ql[0], ql[1], ql[2], ql[3], kh[j16][1], kh[j16][3]);
            }
        }
        __syncthreads();                 // all warps done reading K tile

        if (t + 1 < NT) load_k((t + 1) << 6);

        // ---- online softmax ----
        float mx0 = -1e30f, mx1 = -1e30f;
#pragma unroll
        for (int j = 0; j < 8; j++) {
            S[j][0] *= scale; S[j][1] *= scale;
            S[j][2] *= scale; S[j][3] *= scale;
            mx0 = fmaxf(mx0, fmaxf(S[j][0], S[j][1]));
            mx1 = fmaxf(mx1, fmaxf(S[j][2], S[j][3]));
        }
        mx0 = fmaxf(mx0, __shfl_xor_sync(0xffffffffu, mx0, 1));
        mx0 = fmaxf(mx0, __shfl_xor_sync(0xffffffffu, mx0, 2));
        mx1 = fmaxf(mx1, __shfl_xor_sync(0xffffffffu, mx1, 1));
        mx1 = fmaxf(mx1, __shfl_xor_sync(0xffffffffu, mx1, 2));

        float mn0 = fmaxf(m0, mx0), mn1 = fmaxf(m1, mx1);
        float fac0 = __expf(m0 - mn0), fac1 = __expf(m1 - mn1);
        float rs0 = 0.f, rs1 = 0.f;
#pragma unroll
        for (int j = 0; j < 8; j++) {
            S[j][0] = __expf(S[j][0] - mn0); rs0 += S[j][0];
            S[j][1] = __expf(S[j][1] - mn0); rs0 += S[j][1];
            S[j][2] = __expf(S[j][2] - mn1); rs1 += S[j][2];
            S[j][3] = __expf(S[j][3] - mn1); rs1 += S[j][3];
        }
        rs0 += __shfl_xor_sync(0xffffffffu, rs0, 1);
        rs0 += __shfl_xor_sync(0xffffffffu, rs0, 2);
        rs1 += __shfl_xor_sync(0xffffffffu, rs1, 1);
        rs1 += __shfl_xor_sync(0xffffffffu, rs1, 2);
        l0 = l0 * fac0 + rs0; m0 = mn0;
        l1 = l1 * fac1 + rs1; m1 = mn1;
#pragma unroll
        for (int n = 0; n < 16; n++) {
            o[n][0] *= fac0; o[n][1] *= fac0;
            o[n][2] *= fac1; o[n][3] *= fac1;
        }

        // ---- V(t) ready? ----
        if (t + 1 < NT) asm volatile("cp.async.wait_group 1;" ::: "memory");
        else            asm volatile("cp.async.wait_group 0;" ::: "memory");
        __syncthreads();

        // ---- O += Ph*Vh (single product) ----
#pragma unroll
        for (int kk = 0; kk < 4; kk++) {
            uint32_t ah[4];
            ah[0] = pack_h2(S[2*kk][0],   S[2*kk][1]);
            ah[1] = pack_h2(S[2*kk][2],   S[2*kk][3]);
            ah[2] = pack_h2(S[2*kk+1][0], S[2*kk+1][1]);
            ah[3] = pack_h2(S[2*kk+1][2], S[2*kk+1][3]);
            const uint32_t vrow = (kk*16 + rsel)*AT_ROWB;
#pragma unroll
            for (int db = 0; db < 8; db += 2) {
                uint32_t vh[2][4];
                ldmatrix_x4_t(vh[0], sVh + vrow + (db*16 + csel)*2);
                ldmatrix_x4_t(vh[1], sVh + vrow + ((db+1)*16 + csel)*2);
#pragma unroll
                for (int u = 0; u < 2; u++) {
                    int n = (db+u)*2;
                    mma16816(o[n],   ah[0], ah[1], ah[2], ah[3], vh[u][0], vh[u][1]);
                    mma16816(o[n+1], ah[0], ah[1], ah[2], ah[3], vh[u][2], vh[u][3]);
                }
            }
        }
        __syncthreads();                 // all warps done reading V tile

        if (t + 1 < NT) load_v((t + 1) << 6);
    }

    // ---- epilogue: normalize, split to hi/lo fp16, write ctx ----
    const int g  = lane >> 2;
    const int tg = lane & 3;
    const float inv0 = 1.f / l0;
    const float inv1 = 1.f / l1;
    const int s0 = q0 + wq + g;
    const int s1 = s0 + 8;
#pragma unroll
    for (int n = 0; n < 16; n++) {
        int col = h*DD + 8*n + 2*tg;
        {
            size_t off = (size_t)(b*SS + s0) * EE + col;
            __half h0, l0b, h1, l1b;
            split1(o[n][0] * inv0, h0, l0b);
            split1(o[n][1] * inv0, h1, l1b);
            *(__half2*)&g_ch[off] = __halves2half2(h0, h1);
            *(__half2*)&g_cl[off] = __halves2half2(l0b, l1b);
        }
        {
            size_t off = (size_t)(b*SS + s1) * EE + col;
            __half h0, l0b, h1, l1b;
            split1(o[n][2] * inv1, h0, l0b);
            split1(o[n][3] * inv1, h1, l1b);
            *(__half2*)&g_ch[off] = __halves2half2(h0, h1);
            *(__half2*)&g_cl[off] = __halves2half2(l0b, l1b);
        }
    }
}

// ---------------------------------------------------------------------------
// Launch
// ---------------------------------------------------------------------------
extern "C" void kernel_launch(void* const* d_in, const int* in_sizes, int n_in,
                              void* d_out, int out_size)
{
    (void)in_sizes; (void)n_in; (void)out_size;
    const float* x      = (const float*)d_in[0];
    const float* Wqkv_w = (const float*)d_in[1];
    const float* Wqkv_b = (const float*)d_in[2];
    const float* out_w  = (const float*)d_in[3];
    const float* out_b  = (const float*)d_in[4];
    float* out = (float*)d_out;

    __half *xh, *wqh, *owh, *ch, *cl;
    cudaGetSymbolAddress((void**)&xh,  g_xh);
    cudaGetSymbolAddress((void**)&wqh, g_wqh);
    cudaGetSymbolAddress((void**)&owh, g_owh);
    cudaGetSymbolAddress((void**)&ch,  g_ch);
    cudaGetSymbolAddress((void**)&cl,  g_cl);

    const int QKV_SMEM = GSTAGES * 2 * TILE_BYTES;   // 61440
    const int OUT_SMEM = GSTAGES * 3 * TILE_BYTES;   // 92160

    cudaFuncSetAttribute(attn_mma_kernel, cudaFuncAttributeMaxDynamicSharedMemorySize,
                         ATT_SMEM);
    cudaFuncSetAttribute(gemm_mma<0,1>, cudaFuncAttributeMaxDynamicSharedMemorySize,
                         QKV_SMEM);
    cudaFuncSetAttribute(gemm_mma<1,2>, cudaFuncAttributeMaxDynamicSharedMemorySize,
                         OUT_SMEM);

    rope_table_kernel<<<(SS * 64 + 255) / 256, 256>>>();

    cvt_hi_kernel<<<(MTOT*KDIM/4 + 255) / 256, 256>>>(x, xh, MTOT*KDIM);
    cvt_hi_kernel<<<(NQKV*KDIM/4 + 255) / 256, 256>>>(Wqkv_w, wqh, NQKV*KDIM);
    cvt_hi_kernel<<<(EE*KDIM/4 + 255) / 256, 256>>>(out_w, owh, EE*KDIM);

    gemm_mma<0,1><<<dim3(NQKV/128, MTOT/128), 256, QKV_SMEM>>>(
        xh, nullptr, wqh, Wqkv_b, nullptr, MTOT, NQKV, KDIM);

    rope_split_kernel<<<(2 * BB * HH * SS * 64) / 256, 256>>>();

    attn_mma_kernel<<<dim3(SS/128, HH, BB), 256, ATT_SMEM>>>();

    gemm_mma<1,2><<<dim3(EE/128, MTOT/128), 256, OUT_SMEM>>>(
        ch, cl, owh, out_b, out, MTOT, EE, KDIM);
}

// round 16
// speedup vs baseline: 1.6360x; 1.1151x over previous
#include <cuda_runtime.h>
#include <cuda_fp16.h>
#include <math.h>
#include <stdint.h>

// Problem constants
#define BB   2
#define SS   2048
#define EE   2048
#define HH   16
#define DD   128
#define MTOT (BB*SS)      // 4096
#define NQKV (3*EE)       // 6144
#define KDIM EE           // 2048

// ---------------------------------------------------------------------------
// Scratch (device globals; no allocation allowed)
// ---------------------------------------------------------------------------
__device__ float g_q[(size_t)BB*HH*SS*DD];     // fp32 (pre-RoPE)
__device__ float g_k[(size_t)BB*HH*SS*DD];
__device__ float g_cos[SS*64];
__device__ float g_sin[SS*64];

__device__ __half g_qh[(size_t)BB*HH*SS*DD];   // RoPE'd Q hi
__device__ __half g_ql[(size_t)BB*HH*SS*DD];   // RoPE'd Q lo
__device__ __half g_kh[(size_t)BB*HH*SS*DD];   // RoPE'd K (single-rounded)
__device__ __half g_vh[(size_t)BB*HH*SS*DD];   // V (single-rounded)

__device__ __half g_xh[(size_t)MTOT*KDIM];     // x (single-rounded)
__device__ __half g_wqh[(size_t)NQKV*KDIM];    // Wqkv (single-rounded)
__device__ __half g_owh[(size_t)EE*KDIM];      // out_w (single-rounded)
__device__ __half g_ch[(size_t)MTOT*EE];       // ctx (single-rounded this round)

// ---------------------------------------------------------------------------
// Baseline-PTX helpers (sm_80+)
// ---------------------------------------------------------------------------
__device__ __forceinline__ uint32_t smem_u32(const void* p) {
    uint32_t a;
    asm("{ .reg .u64 t; cvta.to.shared.u64 t, %1; cvt.u32.u64 %0, t; }"
        : "=r"(a) : "l"(p));
    return a;
}

#define CP_ASYNC16(dst, src) \
    asm volatile("cp.async.cg.shared.global [%0], [%1], 16;" \
                 :: "r"(dst), "l"(src) : "memory")
#define CP_COMMIT() asm volatile("cp.async.commit_group;" ::: "memory")

__device__ __forceinline__ void ldmatrix_x4(uint32_t* r, uint32_t addr) {
    asm volatile("ldmatrix.sync.aligned.m8n8.x4.shared.b16 {%0,%1,%2,%3}, [%4];"
                 : "=r"(r[0]), "=r"(r[1]), "=r"(r[2]), "=r"(r[3]) : "r"(addr));
}
__device__ __forceinline__ void ldmatrix_x4_t(uint32_t* r, uint32_t addr) {
    asm volatile("ldmatrix.sync.aligned.m8n8.x4.trans.shared.b16 {%0,%1,%2,%3}, [%4];"
                 : "=r"(r[0]), "=r"(r[1]), "=r"(r[2]), "=r"(r[3]) : "r"(addr));
}

// fp16 inputs, fp32 accumulate
__device__ __forceinline__ void mma16816(float* c,
    uint32_t a0, uint32_t a1, uint32_t a2, uint32_t a3, uint32_t b0, uint32_t b1)
{
    asm volatile(
        "mma.sync.aligned.m16n8k16.row.col.f32.f16.f16.f32 "
        "{%0,%1,%2,%3}, {%4,%5,%6,%7}, {%8,%9}, {%0,%1,%2,%3};"
        : "+f"(c[0]), "+f"(c[1]), "+f"(c[2]), "+f"(c[3])
        : "r"(a0), "r"(a1), "r"(a2), "r"(a3), "r"(b0), "r"(b1));
}

__device__ __forceinline__ void split1(float x, __half& h, __half& l) {
    h = __float2half_rn(x);
    l = __float2half_rn(x - __half2float(h));
}
__device__ __forceinline__ uint32_t pack_h2(float x, float y) {
    __half2 hp = __floats2half2_rn(x, y);
    return *(uint32_t*)&hp;
}

// ---------------------------------------------------------------------------
// fp32 -> fp16 convert (single-rounded)
// ---------------------------------------------------------------------------
__global__ void cvt_hi_kernel(const float* __restrict__ src,
                              __half* __restrict__ hi, int n)
{
    int i4 = (blockIdx.x * blockDim.x + threadIdx.x) << 2;
    if (i4 >= n) return;
    float4 v = *(const float4*)(src + i4);
    __half h[4];
    h[0] = __float2half_rn(v.x); h[1] = __float2half_rn(v.y);
    h[2] = __float2half_rn(v.z); h[3] = __float2half_rn(v.w);
    *(uint2*)(hi + i4) = *(uint2*)h;
}

// ---------------------------------------------------------------------------
// RoPE table
// ---------------------------------------------------------------------------
__global__ void rope_table_kernel()
{
    int idx = blockIdx.x * blockDim.x + threadIdx.x;
    if (idx >= SS * 64) return;
    int j = idx & 63;
    int s = idx >> 6;
    double denom = pow(10000.0, ((double)(2 * j)) / 128.0);
    float invf = (float)(1.0 / denom);
    float ph = (float)s * invf;
    double p = (double)ph;
    g_cos[idx] = (float)cos(p);
    g_sin[idx] = (float)sin(p);
}

// RoPE on fp32 q/k. Q -> (hi, lo) fp16 split; K -> single-rounded fp16.
__global__ void rope_split_kernel()
{
    int idx = blockIdx.x * blockDim.x + threadIdx.x;   // 2*65536*64
    int j      = idx & 63;
    int r      = idx >> 6;
    int bhs    = r & (BB*HH*SS - 1);
    int tensor = r >> 16;
    int s      = bhs & (SS - 1);

    size_t base = (size_t)bhs * DD;
    float c  = g_cos[(s << 6) + j];
    float sn = g_sin[(s << 6) + j];
    if (tensor == 0) {
        float x1 = g_q[base + j];
        float x2 = g_q[base + j + 64];
        float y1 = x1 * c - x2 * sn;
        float y2 = x2 * c + x1 * sn;
        __half h, l;
        split1(y1, h, l); g_qh[base + j] = h;      g_ql[base + j] = l;
        split1(y2, h, l); g_qh[base + j + 64] = h; g_ql[base + j + 64] = l;
    } else {
        float x1 = g_k[base + j];
        float x2 = g_k[base + j + 64];
        float y1 = x1 * c - x2 * sn;
        float y2 = x2 * c + x1 * sn;
        g_kh[base + j]      = __float2half_rn(y1);
        g_kh[base + j + 64] = __float2half_rn(y2);
    }
}

// ---------------------------------------------------------------------------
// mma.sync fp16 GEMM, templated on NPA (number of A parts):
//   NPA=1: C = A*B + bias          (A single-rounded; both projections now)
//   NPA=2: C = Ah*B + Al*B + bias  (A split; unused this round)
// Tile: CTA 128x128, warp 64x32, K-chunk 32, 3-stage cp.async pipeline,
// __launch_bounds__(256, 2) (R14/R15-passing config).
// MODE 0: q,k fp32 + v fp16. MODE 1: C fp32.
// ---------------------------------------------------------------------------
#define GK_CHUNK   32
#define TILE_BYTES 10240            // 128 rows * 80B (32 fp16 + 8 pad)
#define GSTAGES    3

template<int NT>
__device__ __forceinline__ void gemm_load_stage(
    uint32_t stg, const __half* const* tp, int K, int kt, int tid)
{
#pragma unroll
    for (int t = 0; t < NT; t++) {
        const __half* p = tp[t];
#pragma unroll
        for (int i = 0; i < 2; i++) {
            int slot = tid + (i << 8);
            int row  = slot >> 2;
            int c    = slot & 3;
            uint32_t dst = stg + t * TILE_BYTES + row * 80 + c * 16;
            const void* src = p + (size_t)row * K + kt + c * 8;
            CP_ASYNC16(dst, src);
        }
    }
    CP_COMMIT();
}

template<int MODE, int NPA>
__global__ __launch_bounds__(256, 2) void gemm_mma(
    const __half* __restrict__ Ah, const __half* __restrict__ Al,
    const __half* __restrict__ Bh,
    const float* __restrict__ bias, float* __restrict__ C,
    int M, int N, int K)
{
    constexpr int NTILES = NPA + 1;
    constexpr uint32_t STAGE_B = NTILES * TILE_BYTES;

    extern __shared__ char smch[];
    const uint32_t sbase = smem_u32(smch);
    const int tid  = threadIdx.x;
    const int wid  = tid >> 5;
    const int lane = tid & 31;
    const int wm   = wid & 1;
    const int wn   = wid >> 1;
    const int m0   = blockIdx.y << 7;
    const int n0   = blockIdx.x << 7;

    const __half* tp[NTILES];
    tp[0] = Ah + (size_t)m0 * K;
    if (NPA == 2) tp[1] = Al + (size_t)m0 * K;
    tp[NTILES - 1] = Bh + (size_t)n0 * K;

    float c[4][4][4];
#pragma unroll
    for (int i = 0; i < 4; i++)
#pragma unroll
        for (int j = 0; j < 4; j++)
#pragma unroll
            for (int q = 0; q < 4; q++) c[i][j][q] = 0.f;

    const int T = K / GK_CHUNK;

    gemm_load_stage<NTILES>(sbase + 0 * STAGE_B, tp, K, 0 * GK_CHUNK, tid);
    gemm_load_stage<NTILES>(sbase + 1 * STAGE_B, tp, K, 1 * GK_CHUNK, tid);
    gemm_load_stage<NTILES>(sbase + 2 * STAGE_B, tp, K, 2 * GK_CHUNK, tid);

    const int rsel = lane & 15;
    const int csel = (lane >> 4) << 3;

#pragma unroll 1
    for (int t = 0; t < T; t++) {
        int rem = (T - 1) - t;
        if (rem >= 2)      asm volatile("cp.async.wait_group 2;" ::: "memory");
        else if (rem == 1) asm volatile("cp.async.wait_group 1;" ::: "memory");
        else               asm volatile("cp.async.wait_group 0;" ::: "memory");
        __syncthreads();

        const uint32_t stg = sbase + (t % GSTAGES) * STAGE_B;
        const uint32_t aAh = stg;
        const uint32_t aAl = stg + TILE_BYTES;            // valid when NPA==2
        const uint32_t aB  = stg + NPA * TILE_BYTES;

#pragma unroll
        for (int k16 = 0; k16 < 2; k16++) {
            const int koff = (csel + k16*16)*2;
            uint32_t a0[4][4], b[2][4];
#pragma unroll
            for (int i = 0; i < 4; i++)
                ldmatrix_x4(a0[i], aAh + (wm*64 + i*16 + rsel)*80 + koff);
#pragma unroll
            for (int j16 = 0; j16 < 2; j16++)
                ldmatrix_x4(b[j16], aB + (wn*32 + j16*16 + rsel)*80 + koff);
#pragma unroll
            for (int i = 0; i < 4; i++)
#pragma unroll
                for (int j16 = 0; j16 < 2; j16++) {
                    mma16816(c[i][j16*2+0], a0[i][0], a0[i][1], a0[i][2], a0[i][3],
                             b[j16][0], b[j16][2]);
                    mma16816(c[i][j16*2+1], a0[i][0], a0[i][1], a0[i][2], a0[i][3],
                             b[j16][1], b[j16][3]);
                }
            if (NPA == 2) {
                uint32_t a1[4][4];
#pragma unroll
                for (int i = 0; i < 4; i++)
                    ldmatrix_x4(a1[i], aAl + (wm*64 + i*16 + rsel)*80 + koff);
#pragma unroll
                for (int i = 0; i < 4; i++)
#pragma unroll
                    for (int j16 = 0; j16 < 2; j16++) {
                        mma16816(c[i][j16*2+0], a1[i][0], a1[i][1], a1[i][2], a1[i][3],
                                 b[j16][0], b[j16][2]);
                        mma16816(c[i][j16*2+1], a1[i][0], a1[i][1], a1[i][2], a1[i][3],
                                 b[j16][1], b[j16][3]);
                    }
            }
        }
        __syncthreads();
        if (t + 3 < T)
            gemm_load_stage<NTILES>(sbase + ((t+3) % GSTAGES) * STAGE_B,
                                    tp, K, (t+3) * GK_CHUNK, tid);
    }

#pragma unroll
    for (int i = 0; i < 4; i++) {
        int rowA = m0 + wm*64 + i*16 + (lane >> 2);
#pragma unroll
        for (int j = 0; j < 4; j++) {
            int col = n0 + wn*32 + j*8 + (lane & 3)*2;
            float b0 = bias[col], b1 = bias[col+1];
            float2 lo2 = make_float2(c[i][j][0] + b0, c[i][j][1] + b1);
            float2 hi2 = make_float2(c[i][j][2] + b0, c[i][j][3] + b1);
#pragma unroll
            for (int half = 0; half < 2; half++) {
                int row = rowA + half*8;
                float2 v = half ? hi2 : lo2;
                if (MODE == 0) {
                    int which = col >> 11;
                    int h = (col >> 7) & (HH - 1);
                    int d = col & (DD - 1);
                    int bb = row >> 11;
                    int s = row & (SS - 1);
                    size_t off = (((size_t)bb * HH + h) * SS + s) * DD + d;
                    if (which == 2) {
                        __half2 hp = __halves2half2(__float2half_rn(v.x),
                                                    __float2half_rn(v.y));
                        *(__half2*)&g_vh[off] = hp;
                    } else {
                        float* dst = which ? g_k : g_q;
                        *(float2*)&dst[off] = v;
                    }
                } else {
                    *(float2*)&C[(size_t)row * N + col] = v;
                }
            }
        }
    }
}

// ---------------------------------------------------------------------------
// Tensor-core flash attention, fp16 (mainloop unchanged from R14/R15 pass):
//   S = Qh*Kh + Ql*Kh  (Q split, K single-rounded)
//   O += Ph*Vh         (P single-rounded)
// Epilogue now writes ctx single-rounded fp16 (ctx-lo dropped this round).
// ---------------------------------------------------------------------------
#define AT_ROWB  272                    // 128 fp16 + 8 pad
#define Q_BYTES  (128*AT_ROWB)          // 34816
#define KV_TILE  (64*AT_ROWB)           // 17408
#define ATT_SMEM (2*Q_BYTES + 2*KV_TILE)  // 104448

__global__ __launch_bounds__(256, 1) void attn_mma_kernel()
{
    extern __shared__ char smc[];
    const uint32_t sb  = smem_u32(smc);
    const uint32_t sQh = sb;
    const uint32_t sQl = sb + Q_BYTES;
    const uint32_t sKh = sb + 2*Q_BYTES;
    const uint32_t sVh = sKh + KV_TILE;

    const int tid  = threadIdx.x;
    const int wid  = tid >> 5;
    const int lane = tid & 31;
    const int q0 = blockIdx.x << 7;
    const int h  = blockIdx.y;
    const int b  = blockIdx.z;

    const size_t head_off = ((size_t)b * HH + h) * SS * DD;
    const __half* Qhg = g_qh + head_off + (size_t)q0 * DD;
    const __half* Qlg = g_ql + head_off + (size_t)q0 * DD;
    const __half* Khg = g_kh + head_off;
    const __half* Vhg = g_vh + head_off;

    auto load_k = [&](int kt) {
#pragma unroll
        for (int i = 0; i < 4; i++) {
            int idx = tid + (i << 8);          // 0..1023
            int row = idx >> 4, c = idx & 15;
            CP_ASYNC16(sKh + row*AT_ROWB + c*16, Khg + (size_t)(kt+row)*DD + c*8);
        }
        CP_COMMIT();
    };
    auto load_v = [&](int kt) {
#pragma unroll
        for (int i = 0; i < 4; i++) {
            int idx = tid + (i << 8);
            int row = idx >> 4, c = idx & 15;
            CP_ASYNC16(sVh + row*AT_ROWB + c*16, Vhg + (size_t)(kt+row)*DD + c*8);
        }
        CP_COMMIT();
    };

    // ---- prologue: Q (hi+lo) + K0 + V0, one commit group ----
    {
#pragma unroll
        for (int i = 0; i < 8; i++) {
            int cidx = tid + (i << 8);         // 0..2047
            int row = cidx >> 4, c = cidx & 15;
            CP_ASYNC16(sQh + row*AT_ROWB + c*16, Qhg + (size_t)row*DD + c*8);
            CP_ASYNC16(sQl + row*AT_ROWB + c*16, Qlg + (size_t)row*DD + c*8);
        }
#pragma unroll
        for (int i = 0; i < 8; i++) {
            int idx = tid + (i << 8);          // 0..2047: Kh, Vh tiles
            int arr = idx >> 10;               // 0..1
            int row = (idx >> 4) & 63;
            int c   = idx & 15;
            const __half* src = arr ? Vhg : Khg;
            uint32_t dstb = arr ? sVh : sKh;
            CP_ASYNC16(dstb + row*AT_ROWB + c*16, src + (size_t)row*DD + c*8);
        }
        CP_COMMIT();
    }

    float o[16][4];
#pragma unroll
    for (int n = 0; n < 16; n++)
#pragma unroll
        for (int q = 0; q < 4; q++) o[n][q] = 0.f;
    float m0 = -1e30f, m1 = -1e30f, l0 = 0.f, l1 = 0.f;

    const float scale = 0.088388347648318447f;   // 1/sqrt(128)
    const int wq = wid << 4;
    const int rsel = lane & 15;
    const int csel = (lane >> 4) << 3;
    const int NT = SS / 64;                      // 32

#pragma unroll 1
    for (int t = 0; t < NT; t++) {
        // ---- K(t) ready? ----
        if (t == 0) asm volatile("cp.async.wait_group 0;" ::: "memory");
        else        asm volatile("cp.async.wait_group 1;" ::: "memory");
        __syncthreads();

        // ---- scores S = Qh*Kh + Ql*Kh ----
        float S[8][4];
#pragma unroll
        for (int j = 0; j < 8; j++)
#pragma unroll
            for (int q = 0; q < 4; q++) S[j][q] = 0.f;

#pragma unroll
        for (int ds = 0; ds < 8; ds++) {
            const int doff = (ds*16 + csel) * 2;
            uint32_t qh[4], ql[4], kh[4][4];
            ldmatrix_x4(qh, sQh + (wq + rsel)*AT_ROWB + doff);
            ldmatrix_x4(ql, sQl + (wq + rsel)*AT_ROWB + doff);
#pragma unroll
            for (int j16 = 0; j16 < 4; j16++)
                ldmatrix_x4(kh[j16], sKh + (j16*16 + rsel)*AT_ROWB + doff);
#pragma unroll
            for (int j16 = 0; j16 < 4; j16++) {
                mma16816(S[2*j16],   qh[0], qh[1], qh[2], qh[3], kh[j16][0], kh[j16][2]);
                mma16816(S[2*j16+1], qh[0], qh[1], qh[2], qh[3], kh[j16][1], kh[j16][3]);
            }
#pragma unroll
            for (int j16 = 0; j16 < 4; j16++) {
                mma16816(S[2*j16],   ql[0], ql[1], ql[2], ql[3], kh[j16][0], kh[j16][2]);
                mma16816(S[2*j16+1], ql[0], ql[1], ql[2], ql[3], kh[j16][1], kh[j16][3]);
            }
        }
        __syncthreads();                 // all warps done reading K tile

        if (t + 1 < NT) load_k((t + 1) << 6);

        // ---- online softmax ----
        float mx0 = -1e30f, mx1 = -1e30f;
#pragma unroll
        for (int j = 0; j < 8; j++) {
            S[j][0] *= scale; S[j][1] *= scale;
            S[j][2] *= scale; S[j][3] *= scale;
            mx0 = fmaxf(mx0, fmaxf(S[j][0], S[j][1]));
            mx1 = fmaxf(mx1, fmaxf(S[j][2], S[j][3]));
        }
        mx0 = fmaxf(mx0, __shfl_xor_sync(0xffffffffu, mx0, 1));
        mx0 = fmaxf(mx0, __shfl_xor_sync(0xffffffffu, mx0, 2));
        mx1 = fmaxf(mx1, __shfl_xor_sync(0xffffffffu, mx1, 1));
        mx1 = fmaxf(mx1, __shfl_xor_sync(0xffffffffu, mx1, 2));

        float mn0 = fmaxf(m0, mx0), mn1 = fmaxf(m1, mx1);
        float fac0 = __expf(m0 - mn0), fac1 = __expf(m1 - mn1);
        float rs0 = 0.f, rs1 = 0.f;
#pragma unroll
        for (int j = 0; j < 8; j++) {
            S[j][0] = __expf(S[j][0] - mn0); rs0 += S[j][0];
            S[j][1] = __expf(S[j][1] - mn0); rs0 += S[j][1];
            S[j][2] = __expf(S[j][2] - mn1); rs1 += S[j][2];
            S[j][3] = __expf(S[j][3] - mn1); rs1 += S[j][3];
        }
        rs0 += __shfl_xor_sync(0xffffffffu, rs0, 1);
        rs0 += __shfl_xor_sync(0xffffffffu, rs0, 2);
        rs1 += __shfl_xor_sync(0xffffffffu, rs1, 1);
        rs1 += __shfl_xor_sync(0xffffffffu, rs1, 2);
        l0 = l0 * fac0 + rs0; m0 = mn0;
        l1 = l1 * fac1 + rs1; m1 = mn1;
#pragma unroll
        for (int n = 0; n < 16; n++) {
            o[n][0] *= fac0; o[n][1] *= fac0;
            o[n][2] *= fac1; o[n][3] *= fac1;
        }

        // ---- V(t) ready? ----
        if (t + 1 < NT) asm volatile("cp.async.wait_group 1;" ::: "memory");
        else            asm volatile("cp.async.wait_group 0;" ::: "memory");
        __syncthreads();

        // ---- O += Ph*Vh (single product) ----
#pragma unroll
        for (int kk = 0; kk < 4; kk++) {
            uint32_t ah[4];
            ah[0] = pack_h2(S[2*kk][0],   S[2*kk][1]);
            ah[1] = pack_h2(S[2*kk][2],   S[2*kk][3]);
            ah[2] = pack_h2(S[2*kk+1][0], S[2*kk+1][1]);
            ah[3] = pack_h2(S[2*kk+1][2], S[2*kk+1][3]);
            const uint32_t vrow = (kk*16 + rsel)*AT_ROWB;
#pragma unroll
            for (int db = 0; db < 8; db += 2) {
                uint32_t vh[2][4];
                ldmatrix_x4_t(vh[0], sVh + vrow + (db*16 + csel)*2);
                ldmatrix_x4_t(vh[1], sVh + vrow + ((db+1)*16 + csel)*2);
#pragma unroll
                for (int u = 0; u < 2; u++) {
                    int n = (db+u)*2;
                    mma16816(o[n],   ah[0], ah[1], ah[2], ah[3], vh[u][0], vh[u][1]);
                    mma16816(o[n+1], ah[0], ah[1], ah[2], ah[3], vh[u][2], vh[u][3]);
                }
            }
        }
        __syncthreads();                 // all warps done reading V tile

        if (t + 1 < NT) load_v((t + 1) << 6);
    }

    // ---- epilogue: normalize, write ctx single-rounded fp16 ----
    const int g  = lane >> 2;
    const int tg = lane & 3;
    const float inv0 = 1.f / l0;
    const float inv1 = 1.f / l1;
    const int s0 = q0 + wq + g;
    const int s1 = s0 + 8;
#pragma unroll
    for (int n = 0; n < 16; n++) {
        int col = h*DD + 8*n + 2*tg;
        {
            size_t off = (size_t)(b*SS + s0) * EE + col;
            *(uint32_t*)&g_ch[off] = pack_h2(o[n][0] * inv0, o[n][1] * inv0);
        }
        {
            size_t off = (size_t)(b*SS + s1) * EE + col;
            *(uint32_t*)&g_ch[off] = pack_h2(o[n][2] * inv1, o[n][3] * inv1);
        }
    }
}

// ---------------------------------------------------------------------------
// Launch
// ---------------------------------------------------------------------------
extern "C" void kernel_launch(void* const* d_in, const int* in_sizes, int n_in,
                              void* d_out, int out_size)
{
    (void)in_sizes; (void)n_in; (void)out_size;
    const float* x      = (const float*)d_in[0];
    const float* Wqkv_w = (const float*)d_in[1];
    const float* Wqkv_b = (const float*)d_in[2];
    const float* out_w  = (const float*)d_in[3];
    const float* out_b  = (const float*)d_in[4];
    float* out = (float*)d_out;

    __half *xh, *wqh, *owh, *ch;
    cudaGetSymbolAddress((void**)&xh,  g_xh);
    cudaGetSymbolAddress((void**)&wqh, g_wqh);
    cudaGetSymbolAddress((void**)&owh, g_owh);
    cudaGetSymbolAddress((void**)&ch,  g_ch);

    const int P1_SMEM = GSTAGES * 2 * TILE_BYTES;   // 61440 (NPA=1)

    cudaFuncSetAttribute(attn_mma_kernel, cudaFuncAttributeMaxDynamicSharedMemorySize,
                         ATT_SMEM);
    cudaFuncSetAttribute(gemm_mma<0,1>, cudaFuncAttributeMaxDynamicSharedMemorySize,
                         P1_SMEM);
    cudaFuncSetAttribute(gemm_mma<1,1>, cudaFuncAttributeMaxDynamicSharedMemorySize,
                         P1_SMEM);

    rope_table_kernel<<<(SS * 64 + 255) / 256, 256>>>();

    cvt_hi_kernel<<<(MTOT*KDIM/4 + 255) / 256, 256>>>(x, xh, MTOT*KDIM);
    cvt_hi_kernel<<<(NQKV*KDIM/4 + 255) / 256, 256>>>(Wqkv_w, wqh, NQKV*KDIM);
    cvt_hi_kernel<<<(EE*KDIM/4 + 255) / 256, 256>>>(out_w, owh, EE*KDIM);

    gemm_mma<0,1><<<dim3(NQKV/128, MTOT/128), 256, P1_SMEM>>>(
        xh, nullptr, wqh, Wqkv_b, nullptr, MTOT, NQKV, KDIM);

    rope_split_kernel<<<(2 * BB * HH * SS * 64) / 256, 256>>>();

    attn_mma_kernel<<<dim3(SS/128, HH, BB), 256, ATT_SMEM>>>();

    gemm_mma<1,1><<<dim3(EE/128, MTOT/128), 256, P1_SMEM>>>(
        ch, nullptr, owh, out_b, out, MTOT, EE, KDIM);
}

// round 17
// speedup vs baseline: 1.7706x; 1.0823x over previous
#include <cuda_runtime.h>
#include <cuda_fp16.h>
#include <math.h>
#include <stdint.h>

// Problem constants
#define BB   2
#define SS   2048
#define EE   2048
#define HH   16
#define DD   128
#define MTOT (BB*SS)      // 4096
#define NQKV (3*EE)       // 6144
#define KDIM EE           // 2048

// ---------------------------------------------------------------------------
// Scratch (device globals; no allocation allowed)
// ---------------------------------------------------------------------------
__device__ float g_q[(size_t)BB*HH*SS*DD];     // fp32 (pre-RoPE)
__device__ float g_k[(size_t)BB*HH*SS*DD];
__device__ float g_cos[SS*64];
__device__ float g_sin[SS*64];

__device__ __half g_qh[(size_t)BB*HH*SS*DD];   // RoPE'd Q (single-rounded)
__device__ __half g_kh[(size_t)BB*HH*SS*DD];   // RoPE'd K (single-rounded)
__device__ __half g_vh[(size_t)BB*HH*SS*DD];   // V (single-rounded)

__device__ __half g_xh[(size_t)MTOT*KDIM];     // x (single-rounded)
__device__ __half g_wqh[(size_t)NQKV*KDIM];    // Wqkv (single-rounded)
__device__ __half g_owh[(size_t)EE*KDIM];      // out_w (single-rounded)
__device__ __half g_ch[(size_t)MTOT*EE];       // ctx (single-rounded)

// ---------------------------------------------------------------------------
// Baseline-PTX helpers (sm_80+)
// ---------------------------------------------------------------------------
__device__ __forceinline__ uint32_t smem_u32(const void* p) {
    uint32_t a;
    asm("{ .reg .u64 t; cvta.to.shared.u64 t, %1; cvt.u32.u64 %0, t; }"
        : "=r"(a) : "l"(p));
    return a;
}

#define CP_ASYNC16(dst, src) \
    asm volatile("cp.async.cg.shared.global [%0], [%1], 16;" \
                 :: "r"(dst), "l"(src) : "memory")
#define CP_COMMIT() asm volatile("cp.async.commit_group;" ::: "memory")

__device__ __forceinline__ void ldmatrix_x4(uint32_t* r, uint32_t addr) {
    asm volatile("ldmatrix.sync.aligned.m8n8.x4.shared.b16 {%0,%1,%2,%3}, [%4];"
                 : "=r"(r[0]), "=r"(r[1]), "=r"(r[2]), "=r"(r[3]) : "r"(addr));
}
__device__ __forceinline__ void ldmatrix_x4_t(uint32_t* r, uint32_t addr) {
    asm volatile("ldmatrix.sync.aligned.m8n8.x4.trans.shared.b16 {%0,%1,%2,%3}, [%4];"
                 : "=r"(r[0]), "=r"(r[1]), "=r"(r[2]), "=r"(r[3]) : "r"(addr));
}

// fp16 inputs, fp32 accumulate
__device__ __forceinline__ void mma16816(float* c,
    uint32_t a0, uint32_t a1, uint32_t a2, uint32_t a3, uint32_t b0, uint32_t b1)
{
    asm volatile(
        "mma.sync.aligned.m16n8k16.row.col.f32.f16.f16.f32 "
        "{%0,%1,%2,%3}, {%4,%5,%6,%7}, {%8,%9}, {%0,%1,%2,%3};"
        : "+f"(c[0]), "+f"(c[1]), "+f"(c[2]), "+f"(c[3])
        : "r"(a0), "r"(a1), "r"(a2), "r"(a3), "r"(b0), "r"(b1));
}

__device__ __forceinline__ uint32_t pack_h2(float x, float y) {
    __half2 hp = __floats2half2_rn(x, y);
    return *(uint32_t*)&hp;
}

// ---------------------------------------------------------------------------
// fp32 -> fp16 convert (single-rounded)
// ---------------------------------------------------------------------------
__global__ void cvt_hi_kernel(const float* __restrict__ src,
                              __half* __restrict__ hi, int n)
{
    int i4 = (blockIdx.x * blockDim.x + threadIdx.x) << 2;
    if (i4 >= n) return;
    float4 v = *(const float4*)(src + i4);
    __half h[4];
    h[0] = __float2half_rn(v.x); h[1] = __float2half_rn(v.y);
    h[2] = __float2half_rn(v.z); h[3] = __float2half_rn(v.w);
    *(uint2*)(hi + i4) = *(uint2*)h;
}

// ---------------------------------------------------------------------------
// RoPE table
// ---------------------------------------------------------------------------
__global__ void rope_table_kernel()
{
    int idx = blockIdx.x * blockDim.x + threadIdx.x;
    if (idx >= SS * 64) return;
    int j = idx & 63;
    int s = idx >> 6;
    double denom = pow(10000.0, ((double)(2 * j)) / 128.0);
    float invf = (float)(1.0 / denom);
    float ph = (float)s * invf;
    double p = (double)ph;
    g_cos[idx] = (float)cos(p);
    g_sin[idx] = (float)sin(p);
}

// RoPE on fp32 q/k, both written single-rounded fp16.
__global__ void rope_split_kernel()
{
    int idx = blockIdx.x * blockDim.x + threadIdx.x;   // 2*65536*64
    int j      = idx & 63;
    int r      = idx >> 6;
    int bhs    = r & (BB*HH*SS - 1);
    int tensor = r >> 16;
    int s      = bhs & (SS - 1);

    size_t base = (size_t)bhs * DD;
    float c  = g_cos[(s << 6) + j];
    float sn = g_sin[(s << 6) + j];
    const float* src = tensor ? g_k : g_q;
    __half* dst = tensor ? g_kh : g_qh;
    float x1 = src[base + j];
    float x2 = src[base + j + 64];
    float y1 = x1 * c - x2 * sn;
    float y2 = x2 * c + x1 * sn;
    dst[base + j]      = __float2half_rn(y1);
    dst[base + j + 64] = __float2half_rn(y2);
}

// ---------------------------------------------------------------------------
// mma.sync fp16 GEMM, NPA=1 only now: C = A*B + bias (A,B single-rounded).
// Tile: CTA 128x128, warp 64x32, K-chunk 32, 3-stage cp.async pipeline,
// __launch_bounds__(256, 2) (R14/R15/R16-passing config).
// MODE 0: q,k fp32 + v fp16. MODE 1: C fp32.
// ---------------------------------------------------------------------------
#define GK_CHUNK   32
#define TILE_BYTES 10240            // 128 rows * 80B (32 fp16 + 8 pad)
#define GSTAGES    3

template<int NT>
__device__ __forceinline__ void gemm_load_stage(
    uint32_t stg, const __half* const* tp, int K, int kt, int tid)
{
#pragma unroll
    for (int t = 0; t < NT; t++) {
        const __half* p = tp[t];
#pragma unroll
        for (int i = 0; i < 2; i++) {
            int slot = tid + (i << 8);
            int row  = slot >> 2;
            int c    = slot & 3;
            uint32_t dst = stg + t * TILE_BYTES + row * 80 + c * 16;
            const void* src = p + (size_t)row * K + kt + c * 8;
            CP_ASYNC16(dst, src);
        }
    }
    CP_COMMIT();
}

template<int MODE, int NPA>
__global__ __launch_bounds__(256, 2) void gemm_mma(
    const __half* __restrict__ Ah, const __half* __restrict__ Al,
    const __half* __restrict__ Bh,
    const float* __restrict__ bias, float* __restrict__ C,
    int M, int N, int K)
{
    constexpr int NTILES = NPA + 1;
    constexpr uint32_t STAGE_B = NTILES * TILE_BYTES;

    extern __shared__ char smch[];
    const uint32_t sbase = smem_u32(smch);
    const int tid  = threadIdx.x;
    const int wid  = tid >> 5;
    const int lane = tid & 31;
    const int wm   = wid & 1;
    const int wn   = wid >> 1;
    const int m0   = blockIdx.y << 7;
    const int n0   = blockIdx.x << 7;

    const __half* tp[NTILES];
    tp[0] = Ah + (size_t)m0 * K;
    if (NPA == 2) tp[1] = Al + (size_t)m0 * K;
    tp[NTILES - 1] = Bh + (size_t)n0 * K;

    float c[4][4][4];
#pragma unroll
    for (int i = 0; i < 4; i++)
#pragma unroll
        for (int j = 0; j < 4; j++)
#pragma unroll
            for (int q = 0; q < 4; q++) c[i][j][q] = 0.f;

    const int T = K / GK_CHUNK;

    gemm_load_stage<NTILES>(sbase + 0 * STAGE_B, tp, K, 0 * GK_CHUNK, tid);
    gemm_load_stage<NTILES>(sbase + 1 * STAGE_B, tp, K, 1 * GK_CHUNK, tid);
    gemm_load_stage<NTILES>(sbase + 2 * STAGE_B, tp, K, 2 * GK_CHUNK, tid);

    const int rsel = lane & 15;
    const int csel = (lane >> 4) << 3;

#pragma unroll 1
    for (int t = 0; t < T; t++) {
        int rem = (T - 1) - t;
        if (rem >= 2)      asm volatile("cp.async.wait_group 2;" ::: "memory");
        else if (rem == 1) asm volatile("cp.async.wait_group 1;" ::: "memory");
        else               asm volatile("cp.async.wait_group 0;" ::: "memory");
        __syncthreads();

        const uint32_t stg = sbase + (t % GSTAGES) * STAGE_B;
        const uint32_t aAh = stg;
        const uint32_t aAl = stg + TILE_BYTES;            // valid when NPA==2
        const uint32_t aB  = stg + NPA * TILE_BYTES;

#pragma unroll
        for (int k16 = 0; k16 < 2; k16++) {
            const int koff = (csel + k16*16)*2;
            uint32_t a0[4][4], b[2][4];
#pragma unroll
            for (int i = 0; i < 4; i++)
                ldmatrix_x4(a0[i], aAh + (wm*64 + i*16 + rsel)*80 + koff);
#pragma unroll
            for (int j16 = 0; j16 < 2; j16++)
                ldmatrix_x4(b[j16], aB + (wn*32 + j16*16 + rsel)*80 + koff);
#pragma unroll
            for (int i = 0; i < 4; i++)
#pragma unroll
                for (int j16 = 0; j16 < 2; j16++) {
                    mma16816(c[i][j16*2+0], a0[i][0], a0[i][1], a0[i][2], a0[i][3],
                             b[j16][0], b[j16][2]);
                    mma16816(c[i][j16*2+1], a0[i][0], a0[i][1], a0[i][2], a0[i][3],
                             b[j16][1], b[j16][3]);
                }
            if (NPA == 2) {
                uint32_t a1[4][4];
#pragma unroll
                for (int i = 0; i < 4; i++)
                    ldmatrix_x4(a1[i], aAl + (wm*64 + i*16 + rsel)*80 + koff);
#pragma unroll
                for (int i = 0; i < 4; i++)
#pragma unroll
                    for (int j16 = 0; j16 < 2; j16++) {
                        mma16816(c[i][j16*2+0], a1[i][0], a1[i][1], a1[i][2], a1[i][3],
                                 b[j16][0], b[j16][2]);
                        mma16816(c[i][j16*2+1], a1[i][0], a1[i][1], a1[i][2], a1[i][3],
                                 b[j16][1], b[j16][3]);
                    }
            }
        }
        __syncthreads();
        if (t + 3 < T)
            gemm_load_stage<NTILES>(sbase + ((t+3) % GSTAGES) * STAGE_B,
                                    tp, K, (t+3) * GK_CHUNK, tid);
    }

#pragma unroll
    for (int i = 0; i < 4; i++) {
        int rowA = m0 + wm*64 + i*16 + (lane >> 2);
#pragma unroll
        for (int j = 0; j < 4; j++) {
            int col = n0 + wn*32 + j*8 + (lane & 3)*2;
            float b0 = bias[col], b1 = bias[col+1];
            float2 lo2 = make_float2(c[i][j][0] + b0, c[i][j][1] + b1);
            float2 hi2 = make_float2(c[i][j][2] + b0, c[i][j][3] + b1);
#pragma unroll
            for (int half = 0; half < 2; half++) {
                int row = rowA + half*8;
                float2 v = half ? hi2 : lo2;
                if (MODE == 0) {
                    int which = col >> 11;
                    int h = (col >> 7) & (HH - 1);
                    int d = col & (DD - 1);
                    int bb = row >> 11;
                    int s = row & (SS - 1);
                    size_t off = (((size_t)bb * HH + h) * SS + s) * DD + d;
                    if (which == 2) {
                        __half2 hp = __halves2half2(__float2half_rn(v.x),
                                                    __float2half_rn(v.y));
                        *(__half2*)&g_vh[off] = hp;
                    } else {
                        float* dst = which ? g_k : g_q;
                        *(float2*)&dst[off] = v;
                    }
                } else {
                    *(float2*)&C[(size_t)row * N + col] = v;
                }
            }
        }
    }
}

// ---------------------------------------------------------------------------
// Tensor-core flash attention, fp16, all single-product now:
//   S = Q*K^T  (Q, K single-rounded)
//   O += P*V   (P, V single-rounded)
// CTA = 128 q rows x (b,h). 8 warps x 16 q rows. 64-key K/V tiles,
// single-buffered, split-phase pipelined (R6..R16-verified schedule).
// ---------------------------------------------------------------------------
#define AT_ROWB  272                    // 128 fp16 + 8 pad
#define Q_BYTES  (128*AT_ROWB)          // 34816
#define KV_TILE  (64*AT_ROWB)           // 17408
#define ATT_SMEM (Q_BYTES + 2*KV_TILE)  // 69632

__global__ __launch_bounds__(256, 1) void attn_mma_kernel()
{
    extern __shared__ char smc[];
    const uint32_t sb  = smem_u32(smc);
    const uint32_t sQh = sb;
    const uint32_t sKh = sb + Q_BYTES;
    const uint32_t sVh = sKh + KV_TILE;

    const int tid  = threadIdx.x;
    const int wid  = tid >> 5;
    const int lane = tid & 31;
    const int q0 = blockIdx.x << 7;
    const int h  = blockIdx.y;
    const int b  = blockIdx.z;

    const size_t head_off = ((size_t)b * HH + h) * SS * DD;
    const __half* Qhg = g_qh + head_off + (size_t)q0 * DD;
    const __half* Khg = g_kh + head_off;
    const __half* Vhg = g_vh + head_off;

    auto load_k = [&](int kt) {
#pragma unroll
        for (int i = 0; i < 4; i++) {
            int idx = tid + (i << 8);          // 0..1023
            int row = idx >> 4, c = idx & 15;
            CP_ASYNC16(sKh + row*AT_ROWB + c*16, Khg + (size_t)(kt+row)*DD + c*8);
        }
        CP_COMMIT();
    };
    auto load_v = [&](int kt) {
#pragma unroll
        for (int i = 0; i < 4; i++) {
            int idx = tid + (i << 8);
            int row = idx >> 4, c = idx & 15;
            CP_ASYNC16(sVh + row*AT_ROWB + c*16, Vhg + (size_t)(kt+row)*DD + c*8);
        }
        CP_COMMIT();
    };

    // ---- prologue: Q + K0 + V0, one commit group ----
    {
#pragma unroll
        for (int i = 0; i < 8; i++) {
            int cidx = tid + (i << 8);         // 0..2047
            int row = cidx >> 4, c = cidx & 15;
            CP_ASYNC16(sQh + row*AT_ROWB + c*16, Qhg + (size_t)row*DD + c*8);
        }
#pragma unroll
        for (int i = 0; i < 8; i++) {
            int idx = tid + (i << 8);          // 0..2047: Kh, Vh tiles
            int arr = idx >> 10;               // 0..1
            int row = (idx >> 4) & 63;
            int c   = idx & 15;
            const __half* src = arr ? Vhg : Khg;
            uint32_t dstb = arr ? sVh : sKh;
            CP_ASYNC16(dstb + row*AT_ROWB + c*16, src + (size_t)row*DD + c*8);
        }
        CP_COMMIT();
    }

    float o[16][4];
#pragma unroll
    for (int n = 0; n < 16; n++)
#pragma unroll
        for (int q = 0; q < 4; q++) o[n][q] = 0.f;
    float m0 = -1e30f, m1 = -1e30f, l0 = 0.f, l1 = 0.f;

    const float scale = 0.088388347648318447f;   // 1/sqrt(128)
    const int wq = wid << 4;
    const int rsel = lane & 15;
    const int csel = (lane >> 4) << 3;
    const int NT = SS / 64;                      // 32

#pragma unroll 1
    for (int t = 0; t < NT; t++) {
        // ---- K(t) ready? ----
        if (t == 0) asm volatile("cp.async.wait_group 0;" ::: "memory");
        else        asm volatile("cp.async.wait_group 1;" ::: "memory");
        __syncthreads();

        // ---- scores S = Q*K^T (single product) ----
        float S[8][4];
#pragma unroll
        for (int j = 0; j < 8; j++)
#pragma unroll
            for (int q = 0; q < 4; q++) S[j][q] = 0.f;

#pragma unroll
        for (int ds = 0; ds < 8; ds++) {
            const int doff = (ds*16 + csel) * 2;
            uint32_t qh[4], kh[4][4];
            ldmatrix_x4(qh, sQh + (wq + rsel)*AT_ROWB + doff);
#pragma unroll
            for (int j16 = 0; j16 < 4; j16++)
                ldmatrix_x4(kh[j16], sKh + (j16*16 + rsel)*AT_ROWB + doff);
#pragma unroll
            for (int j16 = 0; j16 < 4; j16++) {
                mma16816(S[2*j16],   qh[0], qh[1], qh[2], qh[3], kh[j16][0], kh[j16][2]);
                mma16816(S[2*j16+1], qh[0], qh[1], qh[2], qh[3], kh[j16][1], kh[j16][3]);
            }
        }
        __syncthreads();                 // all warps done reading K tile

        if (t + 1 < NT) load_k((t + 1) << 6);

        // ---- online softmax ----
        float mx0 = -1e30f, mx1 = -1e30f;
#pragma unroll
        for (int j = 0; j < 8; j++) {
            S[j][0] *= scale; S[j][1] *= scale;
            S[j][2] *= scale; S[j][3] *= scale;
            mx0 = fmaxf(mx0, fmaxf(S[j][0], S[j][1]));
            mx1 = fmaxf(mx1, fmaxf(S[j][2], S[j][3]));
        }
        mx0 = fmaxf(mx0, __shfl_xor_sync(0xffffffffu, mx0, 1));
        mx0 = fmaxf(mx0, __shfl_xor_sync(0xffffffffu, mx0, 2));
        mx1 = fmaxf(mx1, __shfl_xor_sync(0xffffffffu, mx1, 1));
        mx1 = fmaxf(mx1, __shfl_xor_sync(0xffffffffu, mx1, 2));

        float mn0 = fmaxf(m0, mx0), mn1 = fmaxf(m1, mx1);
        float fac0 = __expf(m0 - mn0), fac1 = __expf(m1 - mn1);
        float rs0 = 0.f, rs1 = 0.f;
#pragma unroll
        for (int j = 0; j < 8; j++) {
            S[j][0] = __expf(S[j][0] - mn0); rs0 += S[j][0];
            S[j][1] = __expf(S[j][1] - mn0); rs0 += S[j][1];
            S[j][2] = __expf(S[j][2] - mn1); rs1 += S[j][2];
            S[j][3] = __expf(S[j][3] - mn1); rs1 += S[j][3];
        }
        rs0 += __shfl_xor_sync(0xffffffffu, rs0, 1);
        rs0 += __shfl_xor_sync(0xffffffffu, rs0, 2);
        rs1 += __shfl_xor_sync(0xffffffffu, rs1, 1);
        rs1 += __shfl_xor_sync(0xffffffffu, rs1, 2);
        l0 = l0 * fac0 + rs0; m0 = mn0;
        l1 = l1 * fac1 + rs1; m1 = mn1;
#pragma unroll
        for (int n = 0; n < 16; n++) {
            o[n][0] *= fac0; o[n][1] *= fac0;
            o[n][2] *= fac1; o[n][3] *= fac1;
        }

        // ---- V(t) ready? ----
        if (t + 1 < NT) asm volatile("cp.async.wait_group 1;" ::: "memory");
        else            asm volatile("cp.async.wait_group 0;" ::: "memory");
        __syncthreads();

        // ---- O += P*V (single product) ----
#pragma unroll
        for (int kk = 0; kk < 4; kk++) {
            uint32_t ah[4];
            ah[0] = pack_h2(S[2*kk][0],   S[2*kk][1]);
            ah[1] = pack_h2(S[2*kk][2],   S[2*kk][3]);
            ah[2] = pack_h2(S[2*kk+1][0], S[2*kk+1][1]);
            ah[3] = pack_h2(S[2*kk+1][2], S[2*kk+1][3]);
            const uint32_t vrow = (kk*16 + rsel)*AT_ROWB;
#pragma unroll
            for (int db = 0; db < 8; db += 2) {
                uint32_t vh[2][4];
                ldmatrix_x4_t(vh[0], sVh + vrow + (db*16 + csel)*2);
                ldmatrix_x4_t(vh[1], sVh + vrow + ((db+1)*16 + csel)*2);
#pragma unroll
                for (int u = 0; u < 2; u++) {
                    int n = (db+u)*2;
                    mma16816(o[n],   ah[0], ah[1], ah[2], ah[3], vh[u][0], vh[u][1]);
                    mma16816(o[n+1], ah[0], ah[1], ah[2], ah[3], vh[u][2], vh[u][3]);
                }
            }
        }
        __syncthreads();                 // all warps done reading V tile

        if (t + 1 < NT) load_v((t + 1) << 6);
    }

    // ---- epilogue: normalize, write ctx single-rounded fp16 ----
    const int g  = lane >> 2;
    const int tg = lane & 3;
    const float inv0 = 1.f / l0;
    const float inv1 = 1.f / l1;
    const int s0 = q0 + wq + g;
    const int s1 = s0 + 8;
#pragma unroll
    for (int n = 0; n < 16; n++) {
        int col = h*DD + 8*n + 2*tg;
        {
            size_t off = (size_t)(b*SS + s0) * EE + col;
            *(uint32_t*)&g_ch[off] = pack_h2(o[n][0] * inv0, o[n][1] * inv0);
        }
        {
            size_t off = (size_t)(b*SS + s1) * EE + col;
            *(uint32_t*)&g_ch[off] = pack_h2(o[n][2] * inv1, o[n][3] * inv1);
        }
    }
}

// ---------------------------------------------------------------------------
// Launch
// ---------------------------------------------------------------------------
extern "C" void kernel_launch(void* const* d_in, const int* in_sizes, int n_in,
                              void* d_out, int out_size)
{
    (void)in_sizes; (void)n_in; (void)out_size;
    const float* x      = (const float*)d_in[0];
    const float* Wqkv_w = (const float*)d_in[1];
    const float* Wqkv_b = (const float*)d_in[2];
    const float* out_w  = (const float*)d_in[3];
    const float* out_b  = (const float*)d_in[4];
    float* out = (float*)d_out;

    __half *xh, *wqh, *owh, *ch;
    cudaGetSymbolAddress((void**)&xh,  g_xh);
    cudaGetSymbolAddress((void**)&wqh, g_wqh);
    cudaGetSymbolAddress((void**)&owh, g_owh);
    cudaGetSymbolAddress((void**)&ch,  g_ch);

    const int P1_SMEM = GSTAGES * 2 * TILE_BYTES;   // 61440 (NPA=1)

    cudaFuncSetAttribute(attn_mma_kernel, cudaFuncAttributeMaxDynamicSharedMemorySize,
                         ATT_SMEM);
    cudaFuncSetAttribute(gemm_mma<0,1>, cudaFuncAttributeMaxDynamicSharedMemorySize,
                         P1_SMEM);
    cudaFuncSetAttribute(gemm_mma<1,1>, cudaFuncAttributeMaxDynamicSharedMemorySize,
                         P1_SMEM);

    rope_table_kernel<<<(SS * 64 + 255) / 256, 256>>>();

    cvt_hi_kernel<<<(MTOT*KDIM/4 + 255) / 256, 256>>>(x, xh, MTOT*KDIM);
    cvt_hi_kernel<<<(NQKV*KDIM/4 + 255) / 256, 256>>>(Wqkv_w, wqh, NQKV*KDIM);
    cvt_hi_kernel<<<(EE*KDIM/4 + 255) / 256, 256>>>(out_w, owh, EE*KDIM);

    gemm_mma<0,1><<<dim3(NQKV/128, MTOT/128), 256, P1_SMEM>>>(
        xh, nullptr, wqh, Wqkv_b, nullptr, MTOT, NQKV, KDIM);

    rope_split_kernel<<<(2 * BB * HH * SS * 64) / 256, 256>>>();

    attn_mma_kernel<<<dim3(SS/128, HH, BB), 256, ATT_SMEM>>>();

    gemm_mma<1,1><<<dim3(EE/128, MTOT/128), 256, P1_SMEM>>>(
        ch, nullptr, owh, out_b, out, MTOT, EE, KDIM);
}